// round 5
// baseline (speedup 1.0000x reference)
#include <cuda_runtime.h>
#include <math.h>

// Shapes
#define B_ 16
#define C_ 128
#define L_ 1024
#define H_ 8
#define DK_ 16
#define NCONV_ 4
#define NTOK (B_*L_)          // 16384
#define NELEM (B_*L_*C_)      // 2097152

// ---------------- scratch (no allocations allowed) ----------------
__device__ float g_cur[NELEM];
__device__ float g_ln[NELEM];
__device__ float g_t1[NELEM];
__device__ float g_q[NELEM];
__device__ float g_k[NELEM];
__device__ float g_v[NELEM];
__device__ int   g_mask_int;   // 1 => mask stored as int32, 0 => 1-byte

// ---------------- mask dtype detection ----------------
// bool mask (p=0.1 ones): if stored as 1-byte, ~10% of ALL bytes are nonzero.
// If stored as little-endian int32 (values 0/1), bytes at i%4!=0 are ALL zero.
// Reading the first 16384 bytes is safe in both layouts.
__global__ void k_detect_mask(const unsigned char* __restrict__ m) {
    __shared__ int s;
    if (threadIdx.x == 0) s = 0;
    __syncthreads();
    int nz = 0;
    for (int i = threadIdx.x; i < NTOK; i += 256)
        if ((i & 3) && m[i]) nz = 1;
    if (nz) atomicOr(&s, 1);
    __syncthreads();
    if (threadIdx.x == 0) g_mask_int = (s == 0) ? 1 : 0;
}

// ---------------- input transpose [B,C,L] -> [B,L,C] with +pos_encoding ----------------
__global__ void k_in2work(const float* __restrict__ x, float* __restrict__ out) {
    __shared__ float tile[32][33];
    const int b  = blockIdx.z;
    const int l0 = blockIdx.x * 32;
    const int c0 = blockIdx.y * 32;
    const int tx = threadIdx.x, ty = threadIdx.y;
    #pragma unroll
    for (int j = 0; j < 4; j++)
        tile[ty + 8*j][tx] = x[((size_t)b*C_ + (c0 + ty + 8*j))*L_ + l0 + tx];
    __syncthreads();
    // this thread writes channel c = c0+tx for 4 different l
    const int c = c0 + tx;
    const float fi = (float)c;
    float freq, phase;
    if (c & 1) { freq = -powf(10000.f, (1.f - fi) * (1.f/128.f)); phase = 1.57079632679489662f; }
    else       { freq =  powf(10000.f, -fi * (1.f/128.f));        phase = 0.f; }
    #pragma unroll
    for (int j = 0; j < 4; j++) {
        const int l = l0 + ty + 8*j;
        out[((size_t)b*L_ + l)*C_ + c] = tile[tx][ty + 8*j] + sinf((float)l * freq + phase);
    }
}

// ---------------- output transpose [B,L,C] -> [B,C,L] ----------------
__global__ void k_work2out(const float* __restrict__ in, float* __restrict__ out) {
    __shared__ float tile[32][33];
    const int b  = blockIdx.z;
    const int l0 = blockIdx.x * 32;
    const int c0 = blockIdx.y * 32;
    const int tx = threadIdx.x, ty = threadIdx.y;
    #pragma unroll
    for (int j = 0; j < 4; j++)
        tile[ty + 8*j][tx] = in[((size_t)b*L_ + (l0 + ty + 8*j))*C_ + c0 + tx];
    __syncthreads();
    #pragma unroll
    for (int j = 0; j < 4; j++)
        out[((size_t)b*C_ + (c0 + ty + 8*j))*L_ + l0 + tx] = tile[tx][ty + 8*j];
}

// ---------------- LayerNorm over C (one warp per token) ----------------
__global__ void __launch_bounds__(256) k_ln(
    const float* __restrict__ in, const float* __restrict__ g,
    const float* __restrict__ bta, float* __restrict__ out)
{
    const int warp = threadIdx.x >> 5, lane = threadIdx.x & 31;
    const int token = blockIdx.x * 8 + warp;
    const float* p = in + (size_t)token * C_;
    float4 v = ((const float4*)p)[lane];
    float s  = v.x + v.y + v.z + v.w;
    float sq = v.x*v.x + v.y*v.y + v.z*v.z + v.w*v.w;
    #pragma unroll
    for (int off = 16; off; off >>= 1) {
        s  += __shfl_xor_sync(0xffffffffu, s,  off);
        sq += __shfl_xor_sync(0xffffffffu, sq, off);
    }
    const float mean = s * (1.f/128.f);
    const float var  = sq * (1.f/128.f) - mean * mean;
    const float r    = rsqrtf(var + 1e-5f);
    float4 gg = ((const float4*)g)[lane];
    float4 bb = ((const float4*)bta)[lane];
    float4 ov;
    ov.x = (v.x - mean) * r * gg.x + bb.x;
    ov.y = (v.y - mean) * r * gg.y + bb.y;
    ov.z = (v.z - mean) * r * gg.z + bb.z;
    ov.w = (v.w - mean) * r * gg.w + bb.w;
    ((float4*)(out + (size_t)token * C_))[lane] = ov;
}

// ---------------- depthwise conv K=7 along L, pad 3, layout [B,L,C] ----------------
__global__ void __launch_bounds__(256) k_dwconv(
    const float* __restrict__ in, const float* __restrict__ dw, float* __restrict__ out)
{
    __shared__ float w[C_ * 7];
    for (int i = threadIdx.x; i < C_ * 7; i += 256) w[i] = dw[i];
    __syncthreads();
    const int idx = blockIdx.x * 256 + threadIdx.x;   // over B*L*C
    const int c = idx & 127;
    const int l = (idx >> 7) & 1023;
    const float* wp = w + c * 7;
    float acc = 0.f;
    #pragma unroll
    for (int kk = 0; kk < 7; kk++) {
        const int ll = l + kk - 3;
        if (ll >= 0 && ll < L_)
            acc += wp[kk] * in[idx + (kk - 3) * C_];
    }
    out[idx] = acc;
}

// ---------------- SGEMM: out[M,128] = act(A[M,128] @ W[o][c]^T + bias) (+res) ----------------
// BM=64 tokens/block, 256 threads, 8x4 register tile, full K=128 resident.
// Wt smem stride 132 (16B-aligned rows, conflict-free LDS.128 on compute).
template<bool RELU, bool ADDRES>
__global__ void __launch_bounds__(256) k_gemm128(
    const float* __restrict__ A, const float* __restrict__ W,
    const float* __restrict__ bias, const float* __restrict__ res,
    float* __restrict__ out)
{
    extern __shared__ float sm[];
    float* Wt = sm;               // [128][132]  Wt[c*132 + o]
    float* As = sm + 128 * 132;   // [128][68]   As[c*68  + t]
    const int tid = threadIdx.x;
    const int m0 = blockIdx.x * 64;

    for (int i = tid; i < 128 * 128; i += 256) {
        const int o = i >> 7, c = i & 127;
        Wt[c * 132 + o] = W[i];
    }
    for (int i = tid; i < 64 * 128; i += 256) {
        const int t = i >> 7, c = i & 127;
        As[c * 68 + t] = A[(size_t)(m0 + t) * C_ + c];
    }
    __syncthreads();

    const int og = (tid & 31) * 4;   // 4 consecutive output channels
    const int tg = (tid >> 5) * 8;   // 8 consecutive tokens in tile
    float acc[8][4];
    #pragma unroll
    for (int t = 0; t < 8; t++)
        #pragma unroll
        for (int j = 0; j < 4; j++) acc[t][j] = 0.f;

    #pragma unroll 4
    for (int c = 0; c < 128; c++) {
        const float4 w  = *(const float4*)&Wt[c * 132 + og];
        const float4 a0 = *(const float4*)&As[c * 68 + tg];
        const float4 a1 = *(const float4*)&As[c * 68 + tg + 4];
        const float at[8] = {a0.x, a0.y, a0.z, a0.w, a1.x, a1.y, a1.z, a1.w};
        #pragma unroll
        for (int t = 0; t < 8; t++) {
            acc[t][0] += at[t] * w.x;
            acc[t][1] += at[t] * w.y;
            acc[t][2] += at[t] * w.z;
            acc[t][3] += at[t] * w.w;
        }
    }

    const float4 bv = *(const float4*)&bias[og];
    #pragma unroll
    for (int t = 0; t < 8; t++) {
        const int row = m0 + tg + t;
        float4 v;
        v.x = acc[t][0] + bv.x;
        v.y = acc[t][1] + bv.y;
        v.z = acc[t][2] + bv.z;
        v.w = acc[t][3] + bv.w;
        if (RELU) {
            v.x = fmaxf(v.x, 0.f); v.y = fmaxf(v.y, 0.f);
            v.z = fmaxf(v.z, 0.f); v.w = fmaxf(v.w, 0.f);
        }
        if (ADDRES) {
            const float4 r = *(const float4*)&res[(size_t)row * C_ + og];
            v.x += r.x; v.y += r.y; v.z += r.z; v.w += r.w;
        }
        *(float4*)&out[(size_t)row * C_ + og] = v;
    }
}

// ---------------- attention: flash-style, 1 thread = 1 query, 8-key chunked online softmax ----------------
__global__ void __launch_bounds__(128) k_attention(
    const float* __restrict__ Q, const float* __restrict__ K,
    const float* __restrict__ V, const void* __restrict__ maskp,
    float* __restrict__ O)
{
    __shared__ float Ks[128][16];
    __shared__ float Vs[128][16];
    __shared__ float msk[128];
    const int tid = threadIdx.x;
    const int bh = blockIdx.y;            // b*8 + h
    const int b = bh >> 3, h = bh & 7;
    const int ql = blockIdx.x * 128 + tid;

    const float* qp = Q + ((size_t)(b * L_ + ql) * C_ + h * DK_);
    float q[16];
    #pragma unroll
    for (int i = 0; i < 4; i++) {
        const float4 t = *(const float4*)(qp + 4 * i);
        q[4*i] = t.x; q[4*i+1] = t.y; q[4*i+2] = t.z; q[4*i+3] = t.w;
    }
    float o[16];
    #pragma unroll
    for (int d = 0; d < 16; d++) o[d] = 0.f;
    float m = 0.f, ssum = 0.f;   // m init 0 is safe: mnew >= 0 > -1e30 always, so masked p == 0

    const int mint = g_mask_int;
    const int* mi = (const int*)maskp;
    const unsigned char* mu = (const unsigned char*)maskp;

    for (int kt = 0; kt < 8; kt++) {
        const int k0 = kt * 128;
        const float* kb = K + ((size_t)(b * L_ + k0) * C_ + h * DK_);
        const float* vb = V + ((size_t)(b * L_ + k0) * C_ + h * DK_);
        #pragma unroll
        for (int f = tid; f < 512; f += 128) {
            const int key = f >> 2, d4 = (f & 3) * 4;
            *(float4*)&Ks[key][d4] = *(const float4*)(kb + key * C_ + d4);
            *(float4*)&Vs[key][d4] = *(const float4*)(vb + key * C_ + d4);
        }
        {
            const int j = k0 + tid;
            const int mv = mint ? mi[b * L_ + j] : (int)mu[b * L_ + j];
            msk[tid] = mv ? 1.f : 0.f;
        }
        __syncthreads();

        #pragma unroll 1
        for (int ch = 0; ch < 16; ch++) {
            float s[8];
            #pragma unroll
            for (int jj = 0; jj < 8; jj++) {
                const int j = ch * 8 + jj;
                float a = 0.f;
                #pragma unroll
                for (int d = 0; d < 16; d++) a += q[d] * Ks[j][d];
                s[jj] = (msk[j] != 0.f) ? -1e30f : a * 0.25f;
            }
            float cm = s[0];
            #pragma unroll
            for (int jj = 1; jj < 8; jj++) cm = fmaxf(cm, s[jj]);
            const float mnew = fmaxf(m, cm);
            const float corr = __expf(m - mnew);
            ssum *= corr;
            #pragma unroll
            for (int d = 0; d < 16; d++) o[d] *= corr;
            #pragma unroll
            for (int jj = 0; jj < 8; jj++) {
                const int j = ch * 8 + jj;
                const float p = __expf(s[jj] - mnew);
                ssum += p;
                #pragma unroll
                for (int d = 0; d < 16; d++) o[d] += p * Vs[j][d];
            }
            m = mnew;
        }
        __syncthreads();
    }

    const float inv = 1.f / ssum;
    float* op = O + ((size_t)(b * L_ + ql) * C_ + h * DK_);
    #pragma unroll
    for (int i = 0; i < 4; i++) {
        float4 t;
        t.x = o[4*i] * inv; t.y = o[4*i+1] * inv;
        t.z = o[4*i+2] * inv; t.w = o[4*i+3] * inv;
        *(float4*)(op + 4 * i) = t;
    }
}

// ---------------- launcher ----------------
extern "C" void kernel_launch(void* const* d_in, const int* in_sizes, int n_in,
                              void* d_out, int out_size)
{
    const float* x    = (const float*)d_in[0];
    const void*  mask = d_in[1];
    const float* dw_w = (const float*)d_in[2];
    const float* pw_w = (const float*)d_in[3];
    const float* pw_b = (const float*)d_in[4];
    const float* ng   = (const float*)d_in[5];
    const float* nb   = (const float*)d_in[6];
    const float* wq = (const float*)d_in[7];   const float* bq = (const float*)d_in[8];
    const float* wk = (const float*)d_in[9];   const float* bk = (const float*)d_in[10];
    const float* wv = (const float*)d_in[11];  const float* bv = (const float*)d_in[12];
    const float* wo = (const float*)d_in[13];  const float* bo = (const float*)d_in[14];
    const float* w1 = (const float*)d_in[15];  const float* b1 = (const float*)d_in[16];
    const float* w2 = (const float*)d_in[17];  const float* b2 = (const float*)d_in[18];
    float* out = (float*)d_out;

    float *cur, *ln, *t1, *q, *k, *v;
    { void* p; cudaGetSymbolAddress(&p, g_cur); cur = (float*)p; }
    { void* p; cudaGetSymbolAddress(&p, g_ln);  ln  = (float*)p; }
    { void* p; cudaGetSymbolAddress(&p, g_t1);  t1  = (float*)p; }
    { void* p; cudaGetSymbolAddress(&p, g_q);   q   = (float*)p; }
    { void* p; cudaGetSymbolAddress(&p, g_k);   k   = (float*)p; }
    { void* p; cudaGetSymbolAddress(&p, g_v);   v   = (float*)p; }

    const int GS = (128 * 132 + 128 * 68) * 4;   // 102400 B dynamic smem
    cudaFuncSetAttribute(k_gemm128<false,false>, cudaFuncAttributeMaxDynamicSharedMemorySize, GS);
    cudaFuncSetAttribute(k_gemm128<true ,false>, cudaFuncAttributeMaxDynamicSharedMemorySize, GS);
    cudaFuncSetAttribute(k_gemm128<false,true >, cudaFuncAttributeMaxDynamicSharedMemorySize, GS);
    cudaFuncSetAttribute(k_gemm128<true ,true >, cudaFuncAttributeMaxDynamicSharedMemorySize, GS);

    const dim3 tgrid(32, 4, 16), tblk(32, 8);

    k_detect_mask<<<1, 256>>>((const unsigned char*)mask);
    k_in2work<<<tgrid, tblk>>>(x, cur);

    for (int i = 0; i < NCONV_; i++) {
        k_ln<<<2048, 256>>>(cur, ng + i * C_, nb + i * C_, ln);
        k_dwconv<<<NELEM / 256, 256>>>(ln, dw_w + i * C_ * 7, t1);
        // out = relu(pw(dw) + bias) + residual(cur), in-place on cur (element-wise safe)
        k_gemm128<true, true><<<256, 256, GS>>>(t1, pw_w + i * C_ * C_, pw_b + i * C_, cur, cur);
    }

    k_ln<<<2048, 256>>>(cur, ng + NCONV_ * C_, nb + NCONV_ * C_, ln);
    k_gemm128<false, false><<<256, 256, GS>>>(ln, wq, bq, nullptr, q);
    k_gemm128<false, false><<<256, 256, GS>>>(ln, wk, bk, nullptr, k);
    k_gemm128<false, false><<<256, 256, GS>>>(ln, wv, bv, nullptr, v);
    k_attention<<<dim3(8, 128), 128>>>(q, k, v, mask, ln);   // ln reused as attn output
    k_gemm128<false, true><<<256, 256, GS>>>(ln, wo, bo, cur, cur);

    k_ln<<<2048, 256>>>(cur, ng + (NCONV_ + 1) * C_, nb + (NCONV_ + 1) * C_, ln);
    k_gemm128<true , false><<<256, 256, GS>>>(ln, w1, b1, nullptr, t1);
    k_gemm128<false, true ><<<256, 256, GS>>>(t1, w2, b2, cur, cur);

    k_work2out<<<tgrid, tblk>>>(cur, out);
}

// round 6
// speedup vs baseline: 2.6799x; 2.6799x over previous
#include <cuda_runtime.h>
#include <cuda_bf16.h>
#include <math.h>

#define B_ 16
#define C_ 128
#define L_ 1024
#define H_ 8
#define DK_ 16
#define NCONV_ 4
#define NTOK (B_*L_)
#define NELEM (B_*L_*C_)

// ---------------- scratch ----------------
__device__ float g_cur[NELEM];
__device__ float g_ln[NELEM];
__device__ float g_t1[NELEM];
__device__ float g_q[NELEM];
__device__ float g_k[NELEM];
__device__ float g_v[NELEM];
__device__ int   g_mask_int;

// ---------------- mma / ldmatrix helpers ----------------
#define LDMX4(r0,r1,r2,r3,addr) \
  asm volatile("ldmatrix.sync.aligned.m8n8.x4.shared.b16 {%0,%1,%2,%3},[%4];" \
    : "=r"(r0),"=r"(r1),"=r"(r2),"=r"(r3) : "r"(addr))

#define LDMX4T(r0,r1,r2,r3,addr) \
  asm volatile("ldmatrix.sync.aligned.m8n8.x4.trans.shared.b16 {%0,%1,%2,%3},[%4];" \
    : "=r"(r0),"=r"(r1),"=r"(r2),"=r"(r3) : "r"(addr))

#define MMA_BF16_Z(d,a0,a1,a2,a3,b0,b1) \
  asm volatile("mma.sync.aligned.m16n8k16.row.col.f32.bf16.bf16.f32 " \
    "{%0,%1,%2,%3},{%4,%5,%6,%7},{%8,%9},{%10,%11,%12,%13};" \
    : "=f"(d[0]),"=f"(d[1]),"=f"(d[2]),"=f"(d[3]) \
    : "r"(a0),"r"(a1),"r"(a2),"r"(a3),"r"(b0),"r"(b1), \
      "f"(0.f),"f"(0.f),"f"(0.f),"f"(0.f))

#define MMA_BF16(d,a0,a1,a2,a3,b0,b1) \
  asm volatile("mma.sync.aligned.m16n8k16.row.col.f32.bf16.bf16.f32 " \
    "{%0,%1,%2,%3},{%4,%5,%6,%7},{%8,%9},{%0,%1,%2,%3};" \
    : "+f"(d[0]),"+f"(d[1]),"+f"(d[2]),"+f"(d[3]) \
    : "r"(a0),"r"(a1),"r"(a2),"r"(a3),"r"(b0),"r"(b1))

#define MMA_TF32(d,a,b) \
  asm volatile("mma.sync.aligned.m16n8k8.row.col.f32.tf32.tf32.f32 " \
    "{%0,%1,%2,%3},{%4,%5,%6,%7},{%8,%9},{%0,%1,%2,%3};" \
    : "+f"(d[0]),"+f"(d[1]),"+f"(d[2]),"+f"(d[3]) \
    : "r"((a)[0]),"r"((a)[1]),"r"((a)[2]),"r"((a)[3]),"r"((b)[0]),"r"((b)[1]))

__device__ __forceinline__ unsigned cvt_tf32(float f) {
    unsigned u; asm("cvt.rna.tf32.f32 %0,%1;" : "=r"(u) : "f"(f)); return u;
}
__device__ __forceinline__ unsigned pack_bf16(float a, float b) {
    __nv_bfloat162 t = __floats2bfloat162_rn(a, b);
    return *(unsigned*)&t;
}

// ---------------- mask dtype detection ----------------
__global__ void k_detect_mask(const unsigned char* __restrict__ m) {
    __shared__ int s;
    if (threadIdx.x == 0) s = 0;
    __syncthreads();
    int nz = 0;
    for (int i = threadIdx.x; i < NTOK; i += 256)
        if ((i & 3) && m[i]) nz = 1;
    if (nz) atomicOr(&s, 1);
    __syncthreads();
    if (threadIdx.x == 0) g_mask_int = (s == 0) ? 1 : 0;
}

// ---------------- [B,C,L] -> [B,L,C] + pos encoding ----------------
__global__ void k_in2work(const float* __restrict__ x, float* __restrict__ out) {
    __shared__ float tile[32][33];
    const int b  = blockIdx.z;
    const int l0 = blockIdx.x * 32;
    const int c0 = blockIdx.y * 32;
    const int tx = threadIdx.x, ty = threadIdx.y;
    #pragma unroll
    for (int j = 0; j < 4; j++)
        tile[ty + 8*j][tx] = x[((size_t)b*C_ + (c0 + ty + 8*j))*L_ + l0 + tx];
    __syncthreads();
    const int c = c0 + tx;
    const float fi = (float)c;
    float freq, phase;
    if (c & 1) { freq = -powf(10000.f, (1.f - fi) * (1.f/128.f)); phase = 1.57079632679489662f; }
    else       { freq =  powf(10000.f, -fi * (1.f/128.f));        phase = 0.f; }
    #pragma unroll
    for (int j = 0; j < 4; j++) {
        const int l = l0 + ty + 8*j;
        out[((size_t)b*L_ + l)*C_ + c] = tile[tx][ty + 8*j] + sinf((float)l * freq + phase);
    }
}

// ---------------- [B,L,C] -> [B,C,L] ----------------
__global__ void k_work2out(const float* __restrict__ in, float* __restrict__ out) {
    __shared__ float tile[32][33];
    const int b  = blockIdx.z;
    const int l0 = blockIdx.x * 32;
    const int c0 = blockIdx.y * 32;
    const int tx = threadIdx.x, ty = threadIdx.y;
    #pragma unroll
    for (int j = 0; j < 4; j++)
        tile[ty + 8*j][tx] = in[((size_t)b*L_ + (l0 + ty + 8*j))*C_ + c0 + tx];
    __syncthreads();
    #pragma unroll
    for (int j = 0; j < 4; j++)
        out[((size_t)b*C_ + (c0 + ty + 8*j))*L_ + l0 + tx] = tile[tx][ty + 8*j];
}

// ---------------- LayerNorm over C (warp per token) ----------------
__global__ void __launch_bounds__(256) k_ln(
    const float* __restrict__ in, const float* __restrict__ g,
    const float* __restrict__ bta, float* __restrict__ out)
{
    const int warp = threadIdx.x >> 5, lane = threadIdx.x & 31;
    const int token = blockIdx.x * 8 + warp;
    const float* p = in + (size_t)token * C_;
    float4 v = ((const float4*)p)[lane];
    float s  = v.x + v.y + v.z + v.w;
    float sq = v.x*v.x + v.y*v.y + v.z*v.z + v.w*v.w;
    #pragma unroll
    for (int off = 16; off; off >>= 1) {
        s  += __shfl_xor_sync(0xffffffffu, s,  off);
        sq += __shfl_xor_sync(0xffffffffu, sq, off);
    }
    const float mean = s * (1.f/128.f);
    const float var  = sq * (1.f/128.f) - mean * mean;
    const float r    = rsqrtf(var + 1e-5f);
    float4 gg = ((const float4*)g)[lane];
    float4 bb = ((const float4*)bta)[lane];
    float4 ov;
    ov.x = (v.x - mean) * r * gg.x + bb.x;
    ov.y = (v.y - mean) * r * gg.y + bb.y;
    ov.z = (v.z - mean) * r * gg.z + bb.z;
    ov.w = (v.w - mean) * r * gg.w + bb.w;
    ((float4*)(out + (size_t)token * C_))[lane] = ov;
}

// ---------------- depthwise conv K=7, smem-tiled (16 l-positions/block) ----------------
__global__ void __launch_bounds__(256) k_dwconv(
    const float* __restrict__ in, const float* __restrict__ dw, float* __restrict__ out)
{
    __shared__ float sw[C_ * 7];
    __shared__ float si[22 * C_];
    const int tid = threadIdx.x;
    const int b = blockIdx.x >> 6;
    const int l0 = (blockIdx.x & 63) * 16;
    for (int i = tid; i < C_ * 7; i += 256) sw[i] = dw[i];
    for (int i = tid; i < 22 * C_; i += 256) {
        const int r = i >> 7, c = i & 127;
        const int l = l0 - 3 + r;
        si[i] = (l >= 0 && l < L_) ? in[((size_t)b * L_ + l) * C_ + c] : 0.f;
    }
    __syncthreads();
    #pragma unroll
    for (int j = 0; j < 8; j++) {
        const int idx = tid + j * 256;          // 16*128 outputs
        const int r = idx >> 7, c = idx & 127;
        const float* wp = sw + c * 7;
        float acc = 0.f;
        #pragma unroll
        for (int kk = 0; kk < 7; kk++)
            acc += wp[kk] * si[(r + kk) * C_ + c];
        out[((size_t)b * L_ + l0 + r) * C_ + c] = acc;
    }
}

// ---------------- tf32 tensor-core GEMM: out[M,128]=act(A@W^T+b)(+res) ----------------
// BM=128, full K=128, 8 warps (2x4), warp tile 64x32 via m16n8k8.
template<bool RELU, bool ADDRES>
__global__ void __launch_bounds__(256) k_gemm_tf32(
    const float* __restrict__ A, const float* __restrict__ W,
    const float* __restrict__ bias, const float* __restrict__ res,
    float* __restrict__ out)
{
    extern __shared__ float sm[];
    float* As = sm;                // [128][132] tf32 bits
    float* Ws = sm + 128 * 132;    // [128][132]
    const int tid = threadIdx.x;
    const int m0 = blockIdx.x * 128;

    #pragma unroll
    for (int i = 0; i < 16; i++) {
        const int f4 = tid + i * 256;
        const int row = f4 >> 5, c = (f4 & 31) * 4;
        float4 a = *(const float4*)(A + (size_t)(m0 + row) * C_ + c);
        uint4 u;
        u.x = cvt_tf32(a.x); u.y = cvt_tf32(a.y); u.z = cvt_tf32(a.z); u.w = cvt_tf32(a.w);
        *(uint4*)&As[row * 132 + c] = u;
        float4 wv = *(const float4*)(W + (size_t)row * C_ + c);
        uint4 uw;
        uw.x = cvt_tf32(wv.x); uw.y = cvt_tf32(wv.y); uw.z = cvt_tf32(wv.z); uw.w = cvt_tf32(wv.w);
        *(uint4*)&Ws[row * 132 + c] = uw;
    }
    __syncthreads();

    const int w = tid >> 5, l = tid & 31, grp = l >> 2, tig = l & 3;
    const int mw = w >> 2, nw = w & 3;
    float acc[4][4][4];
    #pragma unroll
    for (int mt = 0; mt < 4; mt++)
        #pragma unroll
        for (int nt = 0; nt < 4; nt++)
            #pragma unroll
            for (int q = 0; q < 4; q++) acc[mt][nt][q] = 0.f;

    const unsigned* Au = (const unsigned*)As;
    const unsigned* Wu = (const unsigned*)Ws;

    #pragma unroll
    for (int ks = 0; ks < 16; ks++) {
        const int kb = ks * 8;
        unsigned af[4][4], bf[4][2];
        #pragma unroll
        for (int mt = 0; mt < 4; mt++) {
            const int r = mw * 64 + mt * 16 + grp;
            af[mt][0] = Au[r * 132 + kb + tig];
            af[mt][1] = Au[(r + 8) * 132 + kb + tig];
            af[mt][2] = Au[r * 132 + kb + tig + 4];
            af[mt][3] = Au[(r + 8) * 132 + kb + tig + 4];
        }
        #pragma unroll
        for (int nt = 0; nt < 4; nt++) {
            const int r = nw * 32 + nt * 8 + grp;
            bf[nt][0] = Wu[r * 132 + kb + tig];
            bf[nt][1] = Wu[r * 132 + kb + tig + 4];
        }
        #pragma unroll
        for (int mt = 0; mt < 4; mt++)
            #pragma unroll
            for (int nt = 0; nt < 4; nt++)
                MMA_TF32(acc[mt][nt], af[mt], bf[nt]);
    }

    #pragma unroll
    for (int nt = 0; nt < 4; nt++) {
        const int col = nw * 32 + nt * 8 + tig * 2;
        const float2 bv = *(const float2*)(bias + col);
        #pragma unroll
        for (int mt = 0; mt < 4; mt++) {
            const int row = m0 + mw * 64 + mt * 16 + grp;
            float2 v0 = make_float2(acc[mt][nt][0] + bv.x, acc[mt][nt][1] + bv.y);
            float2 v1 = make_float2(acc[mt][nt][2] + bv.x, acc[mt][nt][3] + bv.y);
            if (RELU) {
                v0.x = fmaxf(v0.x, 0.f); v0.y = fmaxf(v0.y, 0.f);
                v1.x = fmaxf(v1.x, 0.f); v1.y = fmaxf(v1.y, 0.f);
            }
            if (ADDRES) {
                const float2 r0 = *(const float2*)(res + (size_t)row * C_ + col);
                const float2 r1 = *(const float2*)(res + (size_t)(row + 8) * C_ + col);
                v0.x += r0.x; v0.y += r0.y; v1.x += r1.x; v1.y += r1.y;
            }
            *(float2*)(out + (size_t)row * C_ + col) = v0;
            *(float2*)(out + (size_t)(row + 8) * C_ + col) = v1;
        }
    }
}

// ---------------- flash attention, bf16 mma m16n8k16 ----------------
// block: 8 warps x 16 queries = 128 queries; key tiles of 64; grid (8, B*H)
__global__ void __launch_bounds__(256) k_attn(
    const float* __restrict__ Q, const float* __restrict__ K,
    const float* __restrict__ V, const void* __restrict__ maskp,
    float* __restrict__ O)
{
    __shared__ __nv_bfloat16 Qs[128 * 24];
    __shared__ __nv_bfloat16 Ks[64 * 24];
    __shared__ __nv_bfloat16 Vs[64 * 24];
    __shared__ float msk[64];
    const int tid = threadIdx.x;
    const int w = tid >> 5, l = tid & 31;
    const int grp = l >> 2, tig = l & 3;
    const int b = blockIdx.y >> 3, h = blockIdx.y & 7;
    const int q0 = blockIdx.x * 128;
    const int mint = g_mask_int;
    const int* mi = (const int*)maskp;
    const unsigned char* mu = (const unsigned char*)maskp;

    // Q tile, pre-scaled by 1/sqrt(DK)=0.25 (exact in fp32)
    #pragma unroll
    for (int i = tid; i < 512; i += 256) {
        const int row = i >> 2, c4 = (i & 3) * 4;
        float4 f = *(const float4*)(Q + ((size_t)(b * L_ + q0 + row) * C_) + h * 16 + c4);
        __nv_bfloat162* dst = (__nv_bfloat162*)(Qs + row * 24 + c4);
        dst[0] = __floats2bfloat162_rn(f.x * 0.25f, f.y * 0.25f);
        dst[1] = __floats2bfloat162_rn(f.z * 0.25f, f.w * 0.25f);
    }
    __syncthreads();
    unsigned qa0, qa1, qa2, qa3;
    {
        const __nv_bfloat16* p = Qs + (w * 16 + (l & 15)) * 24 + ((l >> 4) * 8);
        unsigned ad = (unsigned)__cvta_generic_to_shared(p);
        LDMX4(qa0, qa1, qa2, qa3, ad);
    }

    float o0[4] = {0,0,0,0}, o1[4] = {0,0,0,0};
    float m0 = 0.f, m1 = 0.f, sum0 = 0.f, sum1 = 0.f;

    for (int kt = 0; kt < 16; kt++) {
        const int k0 = kt * 64;
        {
            const int row = tid >> 2, c4 = (tid & 3) * 4;
            const size_t base = ((size_t)(b * L_ + k0 + row) * C_) + h * 16 + c4;
            float4 fk = *(const float4*)(K + base);
            float4 fv = *(const float4*)(V + base);
            __nv_bfloat162* dk = (__nv_bfloat162*)(Ks + row * 24 + c4);
            dk[0] = __floats2bfloat162_rn(fk.x, fk.y);
            dk[1] = __floats2bfloat162_rn(fk.z, fk.w);
            __nv_bfloat162* dv = (__nv_bfloat162*)(Vs + row * 24 + c4);
            dv[0] = __floats2bfloat162_rn(fv.x, fv.y);
            dv[1] = __floats2bfloat162_rn(fv.z, fv.w);
            if (tid < 64) {
                const int j = k0 + tid;
                const int mv = mint ? mi[b * L_ + j] : (int)mu[b * L_ + j];
                msk[tid] = mv ? -1e30f : 0.f;
            }
        }
        __syncthreads();

        // S = Q K^T  (8 n-tiles of 8 keys)
        float s[8][4];
        #pragma unroll
        for (int ntp = 0; ntp < 4; ntp++) {
            const int nb = ntp * 16;
            const __nv_bfloat16* p = Ks + (nb + ((l >> 4) & 1) * 8 + (l & 7)) * 24 + ((l >> 3) & 1) * 8;
            unsigned ad = (unsigned)__cvta_generic_to_shared(p);
            unsigned kb0, kb1, kb2, kb3;
            LDMX4(kb0, kb1, kb2, kb3, ad);
            MMA_BF16_Z(s[2*ntp],     qa0, qa1, qa2, qa3, kb0, kb1);
            MMA_BF16_Z(s[2*ntp + 1], qa0, qa1, qa2, qa3, kb2, kb3);
        }

        // mask + running max
        float nm0 = m0, nm1 = m1;
        #pragma unroll
        for (int nt = 0; nt < 8; nt++) {
            const float2 mk = *(const float2*)&msk[nt * 8 + tig * 2];
            s[nt][0] += mk.x; s[nt][1] += mk.y;
            s[nt][2] += mk.x; s[nt][3] += mk.y;
            nm0 = fmaxf(nm0, fmaxf(s[nt][0], s[nt][1]));
            nm1 = fmaxf(nm1, fmaxf(s[nt][2], s[nt][3]));
        }
        nm0 = fmaxf(nm0, __shfl_xor_sync(0xffffffffu, nm0, 1));
        nm0 = fmaxf(nm0, __shfl_xor_sync(0xffffffffu, nm0, 2));
        nm1 = fmaxf(nm1, __shfl_xor_sync(0xffffffffu, nm1, 1));
        nm1 = fmaxf(nm1, __shfl_xor_sync(0xffffffffu, nm1, 2));
        const float c0 = __expf(m0 - nm0), c1 = __expf(m1 - nm1);
        m0 = nm0; m1 = nm1;
        sum0 *= c0; sum1 *= c1;
        o0[0] *= c0; o0[1] *= c0; o0[2] *= c1; o0[3] *= c1;
        o1[0] *= c0; o1[1] *= c0; o1[2] *= c1; o1[3] *= c1;

        // exp + row sums + pack P to bf16 A-fragments
        unsigned pa[4][4];
        #pragma unroll
        for (int nt = 0; nt < 8; nt++) {
            const float p0 = __expf(s[nt][0] - nm0), p1 = __expf(s[nt][1] - nm0);
            const float p2 = __expf(s[nt][2] - nm1), p3 = __expf(s[nt][3] - nm1);
            sum0 += p0 + p1; sum1 += p2 + p3;
            pa[nt >> 1][(nt & 1) * 2 + 0] = pack_bf16(p0, p1);
            pa[nt >> 1][(nt & 1) * 2 + 1] = pack_bf16(p2, p3);
        }

        // O += P V
        #pragma unroll
        for (int kk = 0; kk < 4; kk++) {
            const __nv_bfloat16* p = Vs + (kk * 16 + ((l >> 3) & 1) * 8 + (l & 7)) * 24 + ((l >> 4) & 1) * 8;
            unsigned ad = (unsigned)__cvta_generic_to_shared(p);
            unsigned vb0, vb1, vb2, vb3;
            LDMX4T(vb0, vb1, vb2, vb3, ad);
            MMA_BF16(o0, pa[kk][0], pa[kk][1], pa[kk][2], pa[kk][3], vb0, vb1);
            MMA_BF16(o1, pa[kk][0], pa[kk][1], pa[kk][2], pa[kk][3], vb2, vb3);
        }
        __syncthreads();
    }

    sum0 += __shfl_xor_sync(0xffffffffu, sum0, 1);
    sum0 += __shfl_xor_sync(0xffffffffu, sum0, 2);
    sum1 += __shfl_xor_sync(0xffffffffu, sum1, 1);
    sum1 += __shfl_xor_sync(0xffffffffu, sum1, 2);
    const float i0 = 1.f / sum0, i1 = 1.f / sum1;
    const int row0 = q0 + w * 16 + grp, row1 = row0 + 8;
    const int colb = h * 16 + tig * 2;
    *(float2*)(O + (size_t)(b * L_ + row0) * C_ + colb)     = make_float2(o0[0]*i0, o0[1]*i0);
    *(float2*)(O + (size_t)(b * L_ + row1) * C_ + colb)     = make_float2(o0[2]*i1, o0[3]*i1);
    *(float2*)(O + (size_t)(b * L_ + row0) * C_ + colb + 8) = make_float2(o1[0]*i0, o1[1]*i0);
    *(float2*)(O + (size_t)(b * L_ + row1) * C_ + colb + 8) = make_float2(o1[2]*i1, o1[3]*i1);
}

// ---------------- launcher ----------------
extern "C" void kernel_launch(void* const* d_in, const int* in_sizes, int n_in,
                              void* d_out, int out_size)
{
    const float* x    = (const float*)d_in[0];
    const void*  mask = d_in[1];
    const float* dw_w = (const float*)d_in[2];
    const float* pw_w = (const float*)d_in[3];
    const float* pw_b = (const float*)d_in[4];
    const float* ng   = (const float*)d_in[5];
    const float* nb   = (const float*)d_in[6];
    const float* wq = (const float*)d_in[7];   const float* bq = (const float*)d_in[8];
    const float* wk = (const float*)d_in[9];   const float* bk = (const float*)d_in[10];
    const float* wv = (const float*)d_in[11];  const float* bv = (const float*)d_in[12];
    const float* wo = (const float*)d_in[13];  const float* bo = (const float*)d_in[14];
    const float* w1 = (const float*)d_in[15];  const float* b1 = (const float*)d_in[16];
    const float* w2 = (const float*)d_in[17];  const float* b2 = (const float*)d_in[18];
    float* out = (float*)d_out;

    float *cur, *ln, *t1, *q, *k, *v;
    { void* p; cudaGetSymbolAddress(&p, g_cur); cur = (float*)p; }
    { void* p; cudaGetSymbolAddress(&p, g_ln);  ln  = (float*)p; }
    { void* p; cudaGetSymbolAddress(&p, g_t1);  t1  = (float*)p; }
    { void* p; cudaGetSymbolAddress(&p, g_q);   q   = (float*)p; }
    { void* p; cudaGetSymbolAddress(&p, g_k);   k   = (float*)p; }
    { void* p; cudaGetSymbolAddress(&p, g_v);   v   = (float*)p; }

    const int GS = 2 * 128 * 132 * 4;   // 135168 B dynamic smem
    cudaFuncSetAttribute(k_gemm_tf32<false,false>, cudaFuncAttributeMaxDynamicSharedMemorySize, GS);
    cudaFuncSetAttribute(k_gemm_tf32<true ,false>, cudaFuncAttributeMaxDynamicSharedMemorySize, GS);
    cudaFuncSetAttribute(k_gemm_tf32<false,true >, cudaFuncAttributeMaxDynamicSharedMemorySize, GS);
    cudaFuncSetAttribute(k_gemm_tf32<true ,true >, cudaFuncAttributeMaxDynamicSharedMemorySize, GS);

    const dim3 tgrid(32, 4, 16), tblk(32, 8);

    k_detect_mask<<<1, 256>>>((const unsigned char*)mask);
    k_in2work<<<tgrid, tblk>>>(x, cur);

    for (int i = 0; i < NCONV_; i++) {
        k_ln<<<2048, 256>>>(cur, ng + i * C_, nb + i * C_, ln);
        k_dwconv<<<1024, 256>>>(ln, dw_w + i * C_ * 7, t1);
        k_gemm_tf32<true, true><<<128, 256, GS>>>(t1, pw_w + i * C_ * C_, pw_b + i * C_, cur, cur);
    }

    k_ln<<<2048, 256>>>(cur, ng + NCONV_ * C_, nb + NCONV_ * C_, ln);
    k_gemm_tf32<false, false><<<128, 256, GS>>>(ln, wq, bq, nullptr, q);
    k_gemm_tf32<false, false><<<128, 256, GS>>>(ln, wk, bk, nullptr, k);
    k_gemm_tf32<false, false><<<128, 256, GS>>>(ln, wv, bv, nullptr, v);
    k_attn<<<dim3(8, 128), 256>>>(q, k, v, mask, ln);
    k_gemm_tf32<false, true><<<128, 256, GS>>>(ln, wo, bo, cur, cur);

    k_ln<<<2048, 256>>>(cur, ng + (NCONV_ + 1) * C_, nb + (NCONV_ + 1) * C_, ln);
    k_gemm_tf32<true , false><<<128, 256, GS>>>(ln, w1, b1, nullptr, t1);
    k_gemm_tf32<false, true ><<<128, 256, GS>>>(t1, w2, b2, cur, cur);

    k_work2out<<<tgrid, tblk>>>(cur, out);
}

// round 7
// speedup vs baseline: 2.8096x; 1.0484x over previous
#include <cuda_runtime.h>
#include <cuda_bf16.h>
#include <math.h>

#define B_ 16
#define C_ 128
#define L_ 1024
#define H_ 8
#define DK_ 16
#define NCONV_ 4
#define NTOK (B_*L_)
#define NELEM (B_*L_*C_)

// ---------------- scratch ----------------
__device__ float g_cur[NELEM];
__device__ float g_ln[NELEM];
__device__ float g_t1[NELEM];
__device__ float g_q[NELEM];
__device__ float g_k[NELEM];
__device__ float g_v[NELEM];
__device__ int   g_mask_int;

// ---------------- mma / ldmatrix helpers ----------------
#define LDMX4(r0,r1,r2,r3,addr) \
  asm volatile("ldmatrix.sync.aligned.m8n8.x4.shared.b16 {%0,%1,%2,%3},[%4];" \
    : "=r"(r0),"=r"(r1),"=r"(r2),"=r"(r3) : "r"(addr))

#define LDMX4T(r0,r1,r2,r3,addr) \
  asm volatile("ldmatrix.sync.aligned.m8n8.x4.trans.shared.b16 {%0,%1,%2,%3},[%4];" \
    : "=r"(r0),"=r"(r1),"=r"(r2),"=r"(r3) : "r"(addr))

#define MMA_BF16_Z(d,a0,a1,a2,a3,b0,b1) \
  asm volatile("mma.sync.aligned.m16n8k16.row.col.f32.bf16.bf16.f32 " \
    "{%0,%1,%2,%3},{%4,%5,%6,%7},{%8,%9},{%10,%11,%12,%13};" \
    : "=f"(d[0]),"=f"(d[1]),"=f"(d[2]),"=f"(d[3]) \
    : "r"(a0),"r"(a1),"r"(a2),"r"(a3),"r"(b0),"r"(b1), \
      "f"(0.f),"f"(0.f),"f"(0.f),"f"(0.f))

#define MMA_BF16(d,a0,a1,a2,a3,b0,b1) \
  asm volatile("mma.sync.aligned.m16n8k16.row.col.f32.bf16.bf16.f32 " \
    "{%0,%1,%2,%3},{%4,%5,%6,%7},{%8,%9},{%0,%1,%2,%3};" \
    : "+f"(d[0]),"+f"(d[1]),"+f"(d[2]),"+f"(d[3]) \
    : "r"(a0),"r"(a1),"r"(a2),"r"(a3),"r"(b0),"r"(b1))

#define MMA_TF32(d,a,b) \
  asm volatile("mma.sync.aligned.m16n8k8.row.col.f32.tf32.tf32.f32 " \
    "{%0,%1,%2,%3},{%4,%5,%6,%7},{%8,%9},{%0,%1,%2,%3};" \
    : "+f"(d[0]),"+f"(d[1]),"+f"(d[2]),"+f"(d[3]) \
    : "r"((a)[0]),"r"((a)[1]),"r"((a)[2]),"r"((a)[3]),"r"((b)[0]),"r"((b)[1]))

__device__ __forceinline__ unsigned cvt_tf32(float f) {
    unsigned u; asm("cvt.rna.tf32.f32 %0,%1;" : "=r"(u) : "f"(f)); return u;
}
__device__ __forceinline__ unsigned pack_bf16(float a, float b) {
    __nv_bfloat162 t = __floats2bfloat162_rn(a, b);
    return *(unsigned*)&t;
}

// warp-wide LN reduce of a float4 held per-lane (128 elements / row)
__device__ __forceinline__ void ln_row(float4& v, const float4& gg, const float4& gb) {
    float s  = v.x + v.y + v.z + v.w;
    float sq = v.x*v.x + v.y*v.y + v.z*v.z + v.w*v.w;
    #pragma unroll
    for (int off = 16; off; off >>= 1) {
        s  += __shfl_xor_sync(0xffffffffu, s,  off);
        sq += __shfl_xor_sync(0xffffffffu, sq, off);
    }
    const float mean = s * (1.f/128.f);
    const float var  = sq * (1.f/128.f) - mean * mean;
    const float r    = rsqrtf(var + 1e-5f);
    v.x = (v.x - mean) * r * gg.x + gb.x;
    v.y = (v.y - mean) * r * gg.y + gb.y;
    v.z = (v.z - mean) * r * gg.z + gb.z;
    v.w = (v.w - mean) * r * gg.w + gb.w;
}

// ---------------- mask dtype detection ----------------
__global__ void k_detect_mask(const unsigned char* __restrict__ m) {
    __shared__ int s;
    if (threadIdx.x == 0) s = 0;
    __syncthreads();
    int nz = 0;
    for (int i = threadIdx.x; i < NTOK; i += 256)
        if ((i & 3) && m[i]) nz = 1;
    if (nz) atomicOr(&s, 1);
    __syncthreads();
    if (threadIdx.x == 0) g_mask_int = (s == 0) ? 1 : 0;
}

// ---------------- [B,C,L] -> [B,L,C] + pos encoding ----------------
__global__ void k_in2work(const float* __restrict__ x, float* __restrict__ out) {
    __shared__ float tile[32][33];
    const int b  = blockIdx.z;
    const int l0 = blockIdx.x * 32;
    const int c0 = blockIdx.y * 32;
    const int tx = threadIdx.x, ty = threadIdx.y;
    #pragma unroll
    for (int j = 0; j < 4; j++)
        tile[ty + 8*j][tx] = x[((size_t)b*C_ + (c0 + ty + 8*j))*L_ + l0 + tx];
    __syncthreads();
    const int c = c0 + tx;
    const float fi = (float)c;
    float freq, phase;
    if (c & 1) { freq = -powf(10000.f, (1.f - fi) * (1.f/128.f)); phase = 1.57079632679489662f; }
    else       { freq =  powf(10000.f, -fi * (1.f/128.f));        phase = 0.f; }
    #pragma unroll
    for (int j = 0; j < 4; j++) {
        const int l = l0 + ty + 8*j;
        out[((size_t)b*L_ + l)*C_ + c] = tile[tx][ty + 8*j] + sinf((float)l * freq + phase);
    }
}

// ---------------- [B,L,C] -> [B,C,L] ----------------
__global__ void k_work2out(const float* __restrict__ in, float* __restrict__ out) {
    __shared__ float tile[32][33];
    const int b  = blockIdx.z;
    const int l0 = blockIdx.x * 32;
    const int c0 = blockIdx.y * 32;
    const int tx = threadIdx.x, ty = threadIdx.y;
    #pragma unroll
    for (int j = 0; j < 4; j++)
        tile[ty + 8*j][tx] = in[((size_t)b*L_ + (l0 + ty + 8*j))*C_ + c0 + tx];
    __syncthreads();
    #pragma unroll
    for (int j = 0; j < 4; j++)
        out[((size_t)b*C_ + (c0 + ty + 8*j))*L_ + l0 + tx] = tile[tx][ty + 8*j];
}

// =====================================================================
// Fused conv block: out = relu(pointwise(dwconv(LN(in))) + bias) + in
// One block = 128 tokens of one batch. smem: y[134][132] + As + Ws + dwT
// =====================================================================
__global__ void __launch_bounds__(256) k_convblock(
    const float* __restrict__ in, const float* __restrict__ dw,
    const float* __restrict__ pw, const float* __restrict__ pb,
    const float* __restrict__ g,  const float* __restrict__ bb,
    float* __restrict__ out)
{
    extern __shared__ float sm[];
    float* y   = sm;                       // [134][132]
    float* As  = y  + 134 * 132;           // [128][132] tf32
    float* Ws  = As + 128 * 132;           // [128][132] tf32
    float* dwT = Ws + 128 * 132;           // [7][128]
    const int tid = threadIdx.x;
    const int b  = blockIdx.x >> 3;
    const int l0 = (blockIdx.x & 7) * 128;
    const int warp = tid >> 5, lane = tid & 31;

    // --- Phase A: weights + LN'd input rows (with 3-row halo, zero pad) ---
    #pragma unroll
    for (int i = 0; i < 16; i++) {
        const int f4 = tid + i * 256;
        const int row = f4 >> 5, c = (f4 & 31) * 4;
        float4 wv = *(const float4*)(pw + (size_t)row * C_ + c);
        uint4 uw;
        uw.x = cvt_tf32(wv.x); uw.y = cvt_tf32(wv.y); uw.z = cvt_tf32(wv.z); uw.w = cvt_tf32(wv.w);
        *(uint4*)&Ws[row * 132 + c] = uw;
    }
    for (int i = tid; i < 896; i += 256) {
        const int k = i >> 7, c = i & 127;
        dwT[i] = dw[c * 7 + k];
    }
    {
        const float4 gg = *(const float4*)(g  + lane * 4);
        const float4 gb = *(const float4*)(bb + lane * 4);
        for (int r = warp; r < 134; r += 8) {
            const int l = l0 - 3 + r;
            float4 v = make_float4(0.f, 0.f, 0.f, 0.f);
            if (l >= 0 && l < L_) {
                v = *(const float4*)(in + ((size_t)(b * L_ + l)) * C_ + lane * 4);
                ln_row(v, gg, gb);
            } else {
                // still participate in shuffles for warp convergence safety
                ln_row(v, gg, gb);
                v = make_float4(0.f, 0.f, 0.f, 0.f);
            }
            *(float4*)&y[r * 132 + lane * 4] = v;
        }
    }
    __syncthreads();

    // --- Phase B: depthwise conv (7-tap along l), write tf32 to As ---
    {
        const int cw = (tid & 31) * 4;       // 4 channels per thread, lane-major -> conflict-free
        const int lb = (tid >> 5) * 16;      // 16 l-positions per thread
        float4 wk7[7];
        #pragma unroll
        for (int k = 0; k < 7; k++) wk7[k] = *(const float4*)&dwT[k * 128 + cw];
        #pragma unroll
        for (int i = 0; i < 16; i++) {
            const int l = lb + i;
            float4 acc = make_float4(0.f, 0.f, 0.f, 0.f);
            #pragma unroll
            for (int k = 0; k < 7; k++) {
                const float4 yv = *(const float4*)&y[(l + k) * 132 + cw];
                acc.x += wk7[k].x * yv.x;
                acc.y += wk7[k].y * yv.y;
                acc.z += wk7[k].z * yv.z;
                acc.w += wk7[k].w * yv.w;
            }
            uint4 u;
            u.x = cvt_tf32(acc.x); u.y = cvt_tf32(acc.y); u.z = cvt_tf32(acc.z); u.w = cvt_tf32(acc.w);
            *(uint4*)&As[l * 132 + cw] = u;
        }
    }
    __syncthreads();

    // --- Phase C: tf32 MMA pointwise + relu + residual ---
    const int w = warp, l2 = lane, grp = l2 >> 2, tig = l2 & 3;
    const int mw = w >> 2, nw = w & 3;
    float acc[4][4][4];
    #pragma unroll
    for (int mt = 0; mt < 4; mt++)
        #pragma unroll
        for (int nt = 0; nt < 4; nt++)
            #pragma unroll
            for (int q = 0; q < 4; q++) acc[mt][nt][q] = 0.f;

    const unsigned* Au = (const unsigned*)As;
    const unsigned* Wu = (const unsigned*)Ws;
    #pragma unroll
    for (int ks = 0; ks < 16; ks++) {
        const int kb = ks * 8;
        unsigned af[4][4], bf[4][2];
        #pragma unroll
        for (int mt = 0; mt < 4; mt++) {
            const int r = mw * 64 + mt * 16 + grp;
            af[mt][0] = Au[r * 132 + kb + tig];
            af[mt][1] = Au[(r + 8) * 132 + kb + tig];
            af[mt][2] = Au[r * 132 + kb + tig + 4];
            af[mt][3] = Au[(r + 8) * 132 + kb + tig + 4];
        }
        #pragma unroll
        for (int nt = 0; nt < 4; nt++) {
            const int r = nw * 32 + nt * 8 + grp;
            bf[nt][0] = Wu[r * 132 + kb + tig];
            bf[nt][1] = Wu[r * 132 + kb + tig + 4];
        }
        #pragma unroll
        for (int mt = 0; mt < 4; mt++)
            #pragma unroll
            for (int nt = 0; nt < 4; nt++)
                MMA_TF32(acc[mt][nt], af[mt], bf[nt]);
    }

    #pragma unroll
    for (int nt = 0; nt < 4; nt++) {
        const int col = nw * 32 + nt * 8 + tig * 2;
        const float2 bv = *(const float2*)(pb + col);
        #pragma unroll
        for (int mt = 0; mt < 4; mt++) {
            const int rl = mw * 64 + mt * 16 + grp;
            const size_t r0 = (size_t)(b * L_ + l0 + rl) * C_ + col;
            const size_t r1 = (size_t)(b * L_ + l0 + rl + 8) * C_ + col;
            float2 v0 = make_float2(fmaxf(acc[mt][nt][0] + bv.x, 0.f), fmaxf(acc[mt][nt][1] + bv.y, 0.f));
            float2 v1 = make_float2(fmaxf(acc[mt][nt][2] + bv.x, 0.f), fmaxf(acc[mt][nt][3] + bv.y, 0.f));
            const float2 q0 = *(const float2*)(in + r0);
            const float2 q1 = *(const float2*)(in + r1);
            v0.x += q0.x; v0.y += q0.y; v1.x += q1.x; v1.y += q1.y;
            *(float2*)(out + r0) = v0;
            *(float2*)(out + r1) = v1;
        }
    }
}

// =====================================================================
// Generic tf32 GEMM with optional LN-on-load of A, relu, residual.
// =====================================================================
template<bool LNA, bool RELU, bool ADDRES>
__global__ void __launch_bounds__(256) k_gemm_tf32(
    const float* __restrict__ A, const float* __restrict__ W,
    const float* __restrict__ bias, const float* __restrict__ res,
    float* __restrict__ out,
    const float* __restrict__ g, const float* __restrict__ bb)
{
    extern __shared__ float sm[];
    float* As = sm;
    float* Ws = sm + 128 * 132;
    const int tid = threadIdx.x;
    const int m0 = blockIdx.x * 128;
    const int warp = tid >> 5, lane = tid & 31;

    if (LNA) {
        const float4 gg = *(const float4*)(g  + lane * 4);
        const float4 gb = *(const float4*)(bb + lane * 4);
        for (int r = warp; r < 128; r += 8) {
            float4 v = *(const float4*)(A + (size_t)(m0 + r) * C_ + lane * 4);
            ln_row(v, gg, gb);
            uint4 u;
            u.x = cvt_tf32(v.x); u.y = cvt_tf32(v.y); u.z = cvt_tf32(v.z); u.w = cvt_tf32(v.w);
            *(uint4*)&As[r * 132 + lane * 4] = u;
        }
    } else {
        #pragma unroll
        for (int i = 0; i < 16; i++) {
            const int f4 = tid + i * 256;
            const int row = f4 >> 5, c = (f4 & 31) * 4;
            float4 a = *(const float4*)(A + (size_t)(m0 + row) * C_ + c);
            uint4 u;
            u.x = cvt_tf32(a.x); u.y = cvt_tf32(a.y); u.z = cvt_tf32(a.z); u.w = cvt_tf32(a.w);
            *(uint4*)&As[row * 132 + c] = u;
        }
    }
    #pragma unroll
    for (int i = 0; i < 16; i++) {
        const int f4 = tid + i * 256;
        const int row = f4 >> 5, c = (f4 & 31) * 4;
        float4 wv = *(const float4*)(W + (size_t)row * C_ + c);
        uint4 uw;
        uw.x = cvt_tf32(wv.x); uw.y = cvt_tf32(wv.y); uw.z = cvt_tf32(wv.z); uw.w = cvt_tf32(wv.w);
        *(uint4*)&Ws[row * 132 + c] = uw;
    }
    __syncthreads();

    const int grp = lane >> 2, tig = lane & 3;
    const int mw = warp >> 2, nw = warp & 3;
    float acc[4][4][4];
    #pragma unroll
    for (int mt = 0; mt < 4; mt++)
        #pragma unroll
        for (int nt = 0; nt < 4; nt++)
            #pragma unroll
            for (int q = 0; q < 4; q++) acc[mt][nt][q] = 0.f;

    const unsigned* Au = (const unsigned*)As;
    const unsigned* Wu = (const unsigned*)Ws;
    #pragma unroll
    for (int ks = 0; ks < 16; ks++) {
        const int kb = ks * 8;
        unsigned af[4][4], bf[4][2];
        #pragma unroll
        for (int mt = 0; mt < 4; mt++) {
            const int r = mw * 64 + mt * 16 + grp;
            af[mt][0] = Au[r * 132 + kb + tig];
            af[mt][1] = Au[(r + 8) * 132 + kb + tig];
            af[mt][2] = Au[r * 132 + kb + tig + 4];
            af[mt][3] = Au[(r + 8) * 132 + kb + tig + 4];
        }
        #pragma unroll
        for (int nt = 0; nt < 4; nt++) {
            const int r = nw * 32 + nt * 8 + grp;
            bf[nt][0] = Wu[r * 132 + kb + tig];
            bf[nt][1] = Wu[r * 132 + kb + tig + 4];
        }
        #pragma unroll
        for (int mt = 0; mt < 4; mt++)
            #pragma unroll
            for (int nt = 0; nt < 4; nt++)
                MMA_TF32(acc[mt][nt], af[mt], bf[nt]);
    }

    #pragma unroll
    for (int nt = 0; nt < 4; nt++) {
        const int col = nw * 32 + nt * 8 + tig * 2;
        const float2 bv = *(const float2*)(bias + col);
        #pragma unroll
        for (int mt = 0; mt < 4; mt++) {
            const int row = m0 + mw * 64 + mt * 16 + grp;
            float2 v0 = make_float2(acc[mt][nt][0] + bv.x, acc[mt][nt][1] + bv.y);
            float2 v1 = make_float2(acc[mt][nt][2] + bv.x, acc[mt][nt][3] + bv.y);
            if (RELU) {
                v0.x = fmaxf(v0.x, 0.f); v0.y = fmaxf(v0.y, 0.f);
                v1.x = fmaxf(v1.x, 0.f); v1.y = fmaxf(v1.y, 0.f);
            }
            if (ADDRES) {
                const float2 r0 = *(const float2*)(res + (size_t)row * C_ + col);
                const float2 r1 = *(const float2*)(res + (size_t)(row + 8) * C_ + col);
                v0.x += r0.x; v0.y += r0.y; v1.x += r1.x; v1.y += r1.y;
            }
            *(float2*)(out + (size_t)row * C_ + col) = v0;
            *(float2*)(out + (size_t)(row + 8) * C_ + col) = v1;
        }
    }
}

// =====================================================================
// Fused QKV: LN(A) once, three weight matrices, three outputs.
// =====================================================================
__global__ void __launch_bounds__(256) k_qkv3(
    const float* __restrict__ A,
    const float* __restrict__ wq, const float* __restrict__ bq, float* __restrict__ oq,
    const float* __restrict__ wk, const float* __restrict__ bk, float* __restrict__ ok,
    const float* __restrict__ wv, const float* __restrict__ bv, float* __restrict__ ov,
    const float* __restrict__ g, const float* __restrict__ bb)
{
    extern __shared__ float sm[];
    float* As = sm;
    float* Ws = sm + 128 * 132;
    const int tid = threadIdx.x;
    const int m0 = blockIdx.x * 128;
    const int warp = tid >> 5, lane = tid & 31;

    {
        const float4 gg = *(const float4*)(g  + lane * 4);
        const float4 gb = *(const float4*)(bb + lane * 4);
        for (int r = warp; r < 128; r += 8) {
            float4 v = *(const float4*)(A + (size_t)(m0 + r) * C_ + lane * 4);
            ln_row(v, gg, gb);
            uint4 u;
            u.x = cvt_tf32(v.x); u.y = cvt_tf32(v.y); u.z = cvt_tf32(v.z); u.w = cvt_tf32(v.w);
            *(uint4*)&As[r * 132 + lane * 4] = u;
        }
    }

    const float* Wj[3]  = {wq, wk, wv};
    const float* bj[3]  = {bq, bk, bv};
    float*       outj[3] = {oq, ok, ov};

    const int grp = lane >> 2, tig = lane & 3;
    const int mw = warp >> 2, nw = warp & 3;
    const unsigned* Au = (const unsigned*)As;
    const unsigned* Wu = (const unsigned*)Ws;

    #pragma unroll 1
    for (int j = 0; j < 3; j++) {
        __syncthreads();   // As ready (iter 0) / previous Ws reads done
        #pragma unroll
        for (int i = 0; i < 16; i++) {
            const int f4 = tid + i * 256;
            const int row = f4 >> 5, c = (f4 & 31) * 4;
            float4 wv4 = *(const float4*)(Wj[j] + (size_t)row * C_ + c);
            uint4 uw;
            uw.x = cvt_tf32(wv4.x); uw.y = cvt_tf32(wv4.y); uw.z = cvt_tf32(wv4.z); uw.w = cvt_tf32(wv4.w);
            *(uint4*)&Ws[row * 132 + c] = uw;
        }
        __syncthreads();

        float acc[4][4][4];
        #pragma unroll
        for (int mt = 0; mt < 4; mt++)
            #pragma unroll
            for (int nt = 0; nt < 4; nt++)
                #pragma unroll
                for (int q = 0; q < 4; q++) acc[mt][nt][q] = 0.f;

        #pragma unroll
        for (int ks = 0; ks < 16; ks++) {
            const int kb = ks * 8;
            unsigned af[4][4], bf[4][2];
            #pragma unroll
            for (int mt = 0; mt < 4; mt++) {
                const int r = mw * 64 + mt * 16 + grp;
                af[mt][0] = Au[r * 132 + kb + tig];
                af[mt][1] = Au[(r + 8) * 132 + kb + tig];
                af[mt][2] = Au[r * 132 + kb + tig + 4];
                af[mt][3] = Au[(r + 8) * 132 + kb + tig + 4];
            }
            #pragma unroll
            for (int nt = 0; nt < 4; nt++) {
                const int r = nw * 32 + nt * 8 + grp;
                bf[nt][0] = Wu[r * 132 + kb + tig];
                bf[nt][1] = Wu[r * 132 + kb + tig + 4];
            }
            #pragma unroll
            for (int mt = 0; mt < 4; mt++)
                #pragma unroll
                for (int nt = 0; nt < 4; nt++)
                    MMA_TF32(acc[mt][nt], af[mt], bf[nt]);
        }

        #pragma unroll
        for (int nt = 0; nt < 4; nt++) {
            const int col = nw * 32 + nt * 8 + tig * 2;
            const float2 bvv = *(const float2*)(bj[j] + col);
            #pragma unroll
            for (int mt = 0; mt < 4; mt++) {
                const int row = m0 + mw * 64 + mt * 16 + grp;
                float2 v0 = make_float2(acc[mt][nt][0] + bvv.x, acc[mt][nt][1] + bvv.y);
                float2 v1 = make_float2(acc[mt][nt][2] + bvv.x, acc[mt][nt][3] + bvv.y);
                *(float2*)(outj[j] + (size_t)row * C_ + col) = v0;
                *(float2*)(outj[j] + (size_t)(row + 8) * C_ + col) = v1;
            }
        }
    }
}

// ---------------- flash attention, bf16 mma m16n8k16 ----------------
__global__ void __launch_bounds__(256) k_attn(
    const float* __restrict__ Q, const float* __restrict__ K,
    const float* __restrict__ V, const void* __restrict__ maskp,
    float* __restrict__ O)
{
    __shared__ __nv_bfloat16 Qs[128 * 24];
    __shared__ __nv_bfloat16 Ks[64 * 24];
    __shared__ __nv_bfloat16 Vs[64 * 24];
    __shared__ float msk[64];
    const int tid = threadIdx.x;
    const int w = tid >> 5, l = tid & 31;
    const int grp = l >> 2, tig = l & 3;
    const int b = blockIdx.y >> 3, h = blockIdx.y & 7;
    const int q0 = blockIdx.x * 128;
    const int mint = g_mask_int;
    const int* mi = (const int*)maskp;
    const unsigned char* mu = (const unsigned char*)maskp;

    #pragma unroll
    for (int i = tid; i < 512; i += 256) {
        const int row = i >> 2, c4 = (i & 3) * 4;
        float4 f = *(const float4*)(Q + ((size_t)(b * L_ + q0 + row) * C_) + h * 16 + c4);
        __nv_bfloat162* dst = (__nv_bfloat162*)(Qs + row * 24 + c4);
        dst[0] = __floats2bfloat162_rn(f.x * 0.25f, f.y * 0.25f);
        dst[1] = __floats2bfloat162_rn(f.z * 0.25f, f.w * 0.25f);
    }
    __syncthreads();
    unsigned qa0, qa1, qa2, qa3;
    {
        const __nv_bfloat16* p = Qs + (w * 16 + (l & 15)) * 24 + ((l >> 4) * 8);
        unsigned ad = (unsigned)__cvta_generic_to_shared(p);
        LDMX4(qa0, qa1, qa2, qa3, ad);
    }

    float o0[4] = {0,0,0,0}, o1[4] = {0,0,0,0};
    float m0 = 0.f, m1 = 0.f, sum0 = 0.f, sum1 = 0.f;

    for (int kt = 0; kt < 16; kt++) {
        const int k0 = kt * 64;
        {
            const int row = tid >> 2, c4 = (tid & 3) * 4;
            const size_t base = ((size_t)(b * L_ + k0 + row) * C_) + h * 16 + c4;
            float4 fk = *(const float4*)(K + base);
            float4 fv = *(const float4*)(V + base);
            __nv_bfloat162* dk = (__nv_bfloat162*)(Ks + row * 24 + c4);
            dk[0] = __floats2bfloat162_rn(fk.x, fk.y);
            dk[1] = __floats2bfloat162_rn(fk.z, fk.w);
            __nv_bfloat162* dv = (__nv_bfloat162*)(Vs + row * 24 + c4);
            dv[0] = __floats2bfloat162_rn(fv.x, fv.y);
            dv[1] = __floats2bfloat162_rn(fv.z, fv.w);
            if (tid < 64) {
                const int j = k0 + tid;
                const int mv = mint ? mi[b * L_ + j] : (int)mu[b * L_ + j];
                msk[tid] = mv ? -1e30f : 0.f;
            }
        }
        __syncthreads();

        float s[8][4];
        #pragma unroll
        for (int ntp = 0; ntp < 4; ntp++) {
            const int nb = ntp * 16;
            const __nv_bfloat16* p = Ks + (nb + ((l >> 4) & 1) * 8 + (l & 7)) * 24 + ((l >> 3) & 1) * 8;
            unsigned ad = (unsigned)__cvta_generic_to_shared(p);
            unsigned kb0, kb1, kb2, kb3;
            LDMX4(kb0, kb1, kb2, kb3, ad);
            MMA_BF16_Z(s[2*ntp],     qa0, qa1, qa2, qa3, kb0, kb1);
            MMA_BF16_Z(s[2*ntp + 1], qa0, qa1, qa2, qa3, kb2, kb3);
        }

        float nm0 = m0, nm1 = m1;
        #pragma unroll
        for (int nt = 0; nt < 8; nt++) {
            const float2 mk = *(const float2*)&msk[nt * 8 + tig * 2];
            s[nt][0] += mk.x; s[nt][1] += mk.y;
            s[nt][2] += mk.x; s[nt][3] += mk.y;
            nm0 = fmaxf(nm0, fmaxf(s[nt][0], s[nt][1]));
            nm1 = fmaxf(nm1, fmaxf(s[nt][2], s[nt][3]));
        }
        nm0 = fmaxf(nm0, __shfl_xor_sync(0xffffffffu, nm0, 1));
        nm0 = fmaxf(nm0, __shfl_xor_sync(0xffffffffu, nm0, 2));
        nm1 = fmaxf(nm1, __shfl_xor_sync(0xffffffffu, nm1, 1));
        nm1 = fmaxf(nm1, __shfl_xor_sync(0xffffffffu, nm1, 2));
        const float c0 = __expf(m0 - nm0), c1 = __expf(m1 - nm1);
        m0 = nm0; m1 = nm1;
        sum0 *= c0; sum1 *= c1;
        o0[0] *= c0; o0[1] *= c0; o0[2] *= c1; o0[3] *= c1;
        o1[0] *= c0; o1[1] *= c0; o1[2] *= c1; o1[3] *= c1;

        unsigned pa[4][4];
        #pragma unroll
        for (int nt = 0; nt < 8; nt++) {
            const float p0 = __expf(s[nt][0] - nm0), p1 = __expf(s[nt][1] - nm0);
            const float p2 = __expf(s[nt][2] - nm1), p3 = __expf(s[nt][3] - nm1);
            sum0 += p0 + p1; sum1 += p2 + p3;
            pa[nt >> 1][(nt & 1) * 2 + 0] = pack_bf16(p0, p1);
            pa[nt >> 1][(nt & 1) * 2 + 1] = pack_bf16(p2, p3);
        }

        #pragma unroll
        for (int kk = 0; kk < 4; kk++) {
            const __nv_bfloat16* p = Vs + (kk * 16 + ((l >> 3) & 1) * 8 + (l & 7)) * 24 + ((l >> 4) & 1) * 8;
            unsigned ad = (unsigned)__cvta_generic_to_shared(p);
            unsigned vb0, vb1, vb2, vb3;
            LDMX4T(vb0, vb1, vb2, vb3, ad);
            MMA_BF16(o0, pa[kk][0], pa[kk][1], pa[kk][2], pa[kk][3], vb0, vb1);
            MMA_BF16(o1, pa[kk][0], pa[kk][1], pa[kk][2], pa[kk][3], vb2, vb3);
        }
        __syncthreads();
    }

    sum0 += __shfl_xor_sync(0xffffffffu, sum0, 1);
    sum0 += __shfl_xor_sync(0xffffffffu, sum0, 2);
    sum1 += __shfl_xor_sync(0xffffffffu, sum1, 1);
    sum1 += __shfl_xor_sync(0xffffffffu, sum1, 2);
    const float i0 = 1.f / sum0, i1 = 1.f / sum1;
    const int row0 = q0 + w * 16 + grp, row1 = row0 + 8;
    const int colb = h * 16 + tig * 2;
    *(float2*)(O + (size_t)(b * L_ + row0) * C_ + colb)     = make_float2(o0[0]*i0, o0[1]*i0);
    *(float2*)(O + (size_t)(b * L_ + row1) * C_ + colb)     = make_float2(o0[2]*i1, o0[3]*i1);
    *(float2*)(O + (size_t)(b * L_ + row0) * C_ + colb + 8) = make_float2(o1[0]*i0, o1[1]*i0);
    *(float2*)(O + (size_t)(b * L_ + row1) * C_ + colb + 8) = make_float2(o1[2]*i1, o1[3]*i1);
}

// ---------------- launcher ----------------
extern "C" void kernel_launch(void* const* d_in, const int* in_sizes, int n_in,
                              void* d_out, int out_size)
{
    const float* x    = (const float*)d_in[0];
    const void*  mask = d_in[1];
    const float* dw_w = (const float*)d_in[2];
    const float* pw_w = (const float*)d_in[3];
    const float* pw_b = (const float*)d_in[4];
    const float* ng   = (const float*)d_in[5];
    const float* nb   = (const float*)d_in[6];
    const float* wq = (const float*)d_in[7];   const float* bq = (const float*)d_in[8];
    const float* wk = (const float*)d_in[9];   const float* bk = (const float*)d_in[10];
    const float* wv = (const float*)d_in[11];  const float* bv = (const float*)d_in[12];
    const float* wo = (const float*)d_in[13];  const float* bo = (const float*)d_in[14];
    const float* w1 = (const float*)d_in[15];  const float* b1 = (const float*)d_in[16];
    const float* w2 = (const float*)d_in[17];  const float* b2 = (const float*)d_in[18];
    float* out = (float*)d_out;

    float *cur, *ln, *t1, *q, *k, *v;
    { void* p; cudaGetSymbolAddress(&p, g_cur); cur = (float*)p; }
    { void* p; cudaGetSymbolAddress(&p, g_ln);  ln  = (float*)p; }
    { void* p; cudaGetSymbolAddress(&p, g_t1);  t1  = (float*)p; }
    { void* p; cudaGetSymbolAddress(&p, g_q);   q   = (float*)p; }
    { void* p; cudaGetSymbolAddress(&p, g_k);   k   = (float*)p; }
    { void* p; cudaGetSymbolAddress(&p, g_v);   v   = (float*)p; }

    const int SMC = (134 * 132 + 2 * 128 * 132 + 896) * 4;  // 209504 B
    const int SMG = 2 * 128 * 132 * 4;                       // 135168 B
    cudaFuncSetAttribute(k_convblock, cudaFuncAttributeMaxDynamicSharedMemorySize, SMC);
    cudaFuncSetAttribute(k_qkv3, cudaFuncAttributeMaxDynamicSharedMemorySize, SMG);
    cudaFuncSetAttribute(k_gemm_tf32<false,false,true >, cudaFuncAttributeMaxDynamicSharedMemorySize, SMG);
    cudaFuncSetAttribute(k_gemm_tf32<true ,true ,false>, cudaFuncAttributeMaxDynamicSharedMemorySize, SMG);

    const dim3 tgrid(32, 4, 16), tblk(32, 8);

    k_detect_mask<<<1, 256>>>((const unsigned char*)mask);
    k_in2work<<<tgrid, tblk>>>(x, cur);

    // ping-pong: cur -> t1 -> cur -> t1 -> cur
    const float* cin[4]  = {cur, t1, cur, t1};
    float*       cout[4] = {t1, cur, t1, cur};
    for (int i = 0; i < NCONV_; i++) {
        k_convblock<<<128, 256, SMC>>>(cin[i], dw_w + i * C_ * 7, pw_w + i * C_ * C_,
                                       pw_b + i * C_, ng + i * C_, nb + i * C_, cout[i]);
    }

    k_qkv3<<<128, 256, SMG>>>(cur, wq, bq, q, wk, bk, k, wv, bv, v,
                              ng + NCONV_ * C_, nb + NCONV_ * C_);
    k_attn<<<dim3(8, 128), 256>>>(q, k, v, mask, ln);
    k_gemm_tf32<false,false,true ><<<128, 256, SMG>>>(ln, wo, bo, cur, cur, nullptr, nullptr);

    k_gemm_tf32<true ,true ,false><<<128, 256, SMG>>>(cur, w1, b1, nullptr, t1,
                                                      ng + (NCONV_ + 1) * C_, nb + (NCONV_ + 1) * C_);
    k_gemm_tf32<false,false,true ><<<128, 256, SMG>>>(t1, w2, b2, cur, cur, nullptr, nullptr);

    k_work2out<<<tgrid, tblk>>>(cur, out);
}

// round 8
// speedup vs baseline: 3.4716x; 1.2356x over previous
#include <cuda_runtime.h>
#include <cuda_bf16.h>
#include <math.h>

#define B_ 16
#define C_ 128
#define L_ 1024
#define H_ 8
#define DK_ 16
#define NCONV_ 4
#define NTOK (B_*L_)
#define NELEM (B_*L_*C_)

// ---------------- scratch ----------------
__device__ float g_cur[NELEM];
__device__ float g_ln[NELEM];
__device__ float g_t1[NELEM];
__device__ float g_q[NELEM];
__device__ float g_k[NELEM];
__device__ float g_v[NELEM];
__device__ int   g_mask_int;

// ---------------- mma / ldmatrix helpers ----------------
#define LDMX4(r0,r1,r2,r3,addr) \
  asm volatile("ldmatrix.sync.aligned.m8n8.x4.shared.b16 {%0,%1,%2,%3},[%4];" \
    : "=r"(r0),"=r"(r1),"=r"(r2),"=r"(r3) : "r"(addr))

#define LDMX4T(r0,r1,r2,r3,addr) \
  asm volatile("ldmatrix.sync.aligned.m8n8.x4.trans.shared.b16 {%0,%1,%2,%3},[%4];" \
    : "=r"(r0),"=r"(r1),"=r"(r2),"=r"(r3) : "r"(addr))

#define MMA_BF16_Z(d,a0,a1,a2,a3,b0,b1) \
  asm volatile("mma.sync.aligned.m16n8k16.row.col.f32.bf16.bf16.f32 " \
    "{%0,%1,%2,%3},{%4,%5,%6,%7},{%8,%9},{%10,%11,%12,%13};" \
    : "=f"(d[0]),"=f"(d[1]),"=f"(d[2]),"=f"(d[3]) \
    : "r"(a0),"r"(a1),"r"(a2),"r"(a3),"r"(b0),"r"(b1), \
      "f"(0.f),"f"(0.f),"f"(0.f),"f"(0.f))

#define MMA_BF16(d,a0,a1,a2,a3,b0,b1) \
  asm volatile("mma.sync.aligned.m16n8k16.row.col.f32.bf16.bf16.f32 " \
    "{%0,%1,%2,%3},{%4,%5,%6,%7},{%8,%9},{%0,%1,%2,%3};" \
    : "+f"(d[0]),"+f"(d[1]),"+f"(d[2]),"+f"(d[3]) \
    : "r"(a0),"r"(a1),"r"(a2),"r"(a3),"r"(b0),"r"(b1))

#define MMA_TF32(d,a,b) \
  asm volatile("mma.sync.aligned.m16n8k8.row.col.f32.tf32.tf32.f32 " \
    "{%0,%1,%2,%3},{%4,%5,%6,%7},{%8,%9},{%0,%1,%2,%3};" \
    : "+f"(d[0]),"+f"(d[1]),"+f"(d[2]),"+f"(d[3]) \
    : "r"((a)[0]),"r"((a)[1]),"r"((a)[2]),"r"((a)[3]),"r"((b)[0]),"r"((b)[1]))

__device__ __forceinline__ unsigned cvt_tf32(float f) {
    unsigned u; asm("cvt.rna.tf32.f32 %0,%1;" : "=r"(u) : "f"(f)); return u;
}
__device__ __forceinline__ unsigned pack_bf16(float a, float b) {
    __nv_bfloat162 t = __floats2bfloat162_rn(a, b);
    return *(unsigned*)&t;
}

__device__ __forceinline__ void ln_row(float4& v, const float4& gg, const float4& gb) {
    float s  = v.x + v.y + v.z + v.w;
    float sq = v.x*v.x + v.y*v.y + v.z*v.z + v.w*v.w;
    #pragma unroll
    for (int off = 16; off; off >>= 1) {
        s  += __shfl_xor_sync(0xffffffffu, s,  off);
        sq += __shfl_xor_sync(0xffffffffu, sq, off);
    }
    const float mean = s * (1.f/128.f);
    const float var  = sq * (1.f/128.f) - mean * mean;
    const float r    = rsqrtf(var + 1e-5f);
    v.x = (v.x - mean) * r * gg.x + gb.x;
    v.y = (v.y - mean) * r * gg.y + gb.y;
    v.z = (v.z - mean) * r * gg.z + gb.z;
    v.w = (v.w - mean) * r * gg.w + gb.w;
}

// 16-warp tf32 MMA over As[128][132] x Ws[128][132] -> acc[2][4][4]
// warp tile 32x32: mw=warp>>2 (rows), nw=warp&3 (cols)
__device__ __forceinline__ void mma_128x128(
    const unsigned* Au, const unsigned* Wu, int mw, int nw, int grp, int tig,
    float acc[2][4][4])
{
    #pragma unroll
    for (int ks = 0; ks < 16; ks++) {
        const int kb = ks * 8;
        unsigned af[2][4], bf[4][2];
        #pragma unroll
        for (int mt = 0; mt < 2; mt++) {
            const int r = mw * 32 + mt * 16 + grp;
            af[mt][0] = Au[r * 132 + kb + tig];
            af[mt][1] = Au[(r + 8) * 132 + kb + tig];
            af[mt][2] = Au[r * 132 + kb + tig + 4];
            af[mt][3] = Au[(r + 8) * 132 + kb + tig + 4];
        }
        #pragma unroll
        for (int nt = 0; nt < 4; nt++) {
            const int r = nw * 32 + nt * 8 + grp;
            bf[nt][0] = Wu[r * 132 + kb + tig];
            bf[nt][1] = Wu[r * 132 + kb + tig + 4];
        }
        #pragma unroll
        for (int mt = 0; mt < 2; mt++)
            #pragma unroll
            for (int nt = 0; nt < 4; nt++)
                MMA_TF32(acc[mt][nt], af[mt], bf[nt]);
    }
}

// ---------------- mask dtype detection ----------------
__global__ void k_detect_mask(const unsigned char* __restrict__ m) {
    __shared__ int s;
    if (threadIdx.x == 0) s = 0;
    __syncthreads();
    int nz = 0;
    for (int i = threadIdx.x; i < NTOK; i += 256)
        if ((i & 3) && m[i]) nz = 1;
    if (nz) atomicOr(&s, 1);
    __syncthreads();
    if (threadIdx.x == 0) g_mask_int = (s == 0) ? 1 : 0;
}

// ---------------- [B,C,L] -> [B,L,C] + pos encoding ----------------
__global__ void k_in2work(const float* __restrict__ x, float* __restrict__ out) {
    __shared__ float tile[32][33];
    const int b  = blockIdx.z;
    const int l0 = blockIdx.x * 32;
    const int c0 = blockIdx.y * 32;
    const int tx = threadIdx.x, ty = threadIdx.y;
    #pragma unroll
    for (int j = 0; j < 4; j++)
        tile[ty + 8*j][tx] = x[((size_t)b*C_ + (c0 + ty + 8*j))*L_ + l0 + tx];
    __syncthreads();
    const int c = c0 + tx;
    const float fi = (float)c;
    float freq, phase;
    if (c & 1) { freq = -powf(10000.f, (1.f - fi) * (1.f/128.f)); phase = 1.57079632679489662f; }
    else       { freq =  powf(10000.f, -fi * (1.f/128.f));        phase = 0.f; }
    #pragma unroll
    for (int j = 0; j < 4; j++) {
        const int l = l0 + ty + 8*j;
        out[((size_t)b*L_ + l)*C_ + c] = tile[tx][ty + 8*j] + sinf((float)l * freq + phase);
    }
}

// ---------------- [B,L,C] -> [B,C,L] ----------------
__global__ void k_work2out(const float* __restrict__ in, float* __restrict__ out) {
    __shared__ float tile[32][33];
    const int b  = blockIdx.z;
    const int l0 = blockIdx.x * 32;
    const int c0 = blockIdx.y * 32;
    const int tx = threadIdx.x, ty = threadIdx.y;
    #pragma unroll
    for (int j = 0; j < 4; j++)
        tile[ty + 8*j][tx] = in[((size_t)b*L_ + (l0 + ty + 8*j))*C_ + c0 + tx];
    __syncthreads();
    #pragma unroll
    for (int j = 0; j < 4; j++)
        out[((size_t)b*C_ + (c0 + ty + 8*j))*L_ + l0 + tx] = tile[tx][ty + 8*j];
}

// =====================================================================
// Fused conv block, 512 threads / 16 warps
// =====================================================================
__global__ void __launch_bounds__(512) k_convblock(
    const float* __restrict__ in, const float* __restrict__ dw,
    const float* __restrict__ pw, const float* __restrict__ pb,
    const float* __restrict__ g,  const float* __restrict__ bb,
    float* __restrict__ out)
{
    extern __shared__ float sm[];
    float* y   = sm;                       // [134][132]
    float* As  = y  + 134 * 132;           // [128][132] tf32
    float* Ws  = As + 128 * 132;           // [128][132] tf32
    float* dwT = Ws + 128 * 132;           // [7][128]
    const int tid = threadIdx.x;
    const int b  = blockIdx.x >> 3;
    const int l0 = (blockIdx.x & 7) * 128;
    const int warp = tid >> 5, lane = tid & 31;

    #pragma unroll
    for (int i = 0; i < 8; i++) {
        const int f4 = tid + i * 512;
        const int row = f4 >> 5, c = (f4 & 31) * 4;
        float4 wv = *(const float4*)(pw + (size_t)row * C_ + c);
        uint4 uw;
        uw.x = cvt_tf32(wv.x); uw.y = cvt_tf32(wv.y); uw.z = cvt_tf32(wv.z); uw.w = cvt_tf32(wv.w);
        *(uint4*)&Ws[row * 132 + c] = uw;
    }
    for (int i = tid; i < 896; i += 512) {
        const int k = i >> 7, c = i & 127;
        dwT[i] = dw[c * 7 + k];
    }
    {
        const float4 gg = *(const float4*)(g  + lane * 4);
        const float4 gb = *(const float4*)(bb + lane * 4);
        for (int r = warp; r < 134; r += 16) {
            const int l = l0 - 3 + r;
            float4 v = make_float4(0.f, 0.f, 0.f, 0.f);
            if (l >= 0 && l < L_) {
                v = *(const float4*)(in + ((size_t)(b * L_ + l)) * C_ + lane * 4);
                ln_row(v, gg, gb);
            } else {
                ln_row(v, gg, gb);
                v = make_float4(0.f, 0.f, 0.f, 0.f);
            }
            *(float4*)&y[r * 132 + lane * 4] = v;
        }
    }
    __syncthreads();

    // depthwise conv: each thread 4 channels x 8 l-positions
    {
        const int cw = lane * 4;
        const int lb = warp * 8;
        float4 wk7[7];
        #pragma unroll
        for (int k = 0; k < 7; k++) wk7[k] = *(const float4*)&dwT[k * 128 + cw];
        #pragma unroll
        for (int i = 0; i < 8; i++) {
            const int l = lb + i;
            float4 acc = make_float4(0.f, 0.f, 0.f, 0.f);
            #pragma unroll
            for (int k = 0; k < 7; k++) {
                const float4 yv = *(const float4*)&y[(l + k) * 132 + cw];
                acc.x += wk7[k].x * yv.x;
                acc.y += wk7[k].y * yv.y;
                acc.z += wk7[k].z * yv.z;
                acc.w += wk7[k].w * yv.w;
            }
            uint4 u;
            u.x = cvt_tf32(acc.x); u.y = cvt_tf32(acc.y); u.z = cvt_tf32(acc.z); u.w = cvt_tf32(acc.w);
            *(uint4*)&As[l * 132 + cw] = u;
        }
    }
    __syncthreads();

    const int grp = lane >> 2, tig = lane & 3;
    const int mw = warp >> 2, nw = warp & 3;
    float acc[2][4][4];
    #pragma unroll
    for (int mt = 0; mt < 2; mt++)
        #pragma unroll
        for (int nt = 0; nt < 4; nt++)
            #pragma unroll
            for (int q = 0; q < 4; q++) acc[mt][nt][q] = 0.f;

    mma_128x128((const unsigned*)As, (const unsigned*)Ws, mw, nw, grp, tig, acc);

    #pragma unroll
    for (int nt = 0; nt < 4; nt++) {
        const int col = nw * 32 + nt * 8 + tig * 2;
        const float2 bv = *(const float2*)(pb + col);
        #pragma unroll
        for (int mt = 0; mt < 2; mt++) {
            const int rl = mw * 32 + mt * 16 + grp;
            const size_t r0 = (size_t)(b * L_ + l0 + rl) * C_ + col;
            const size_t r1 = (size_t)(b * L_ + l0 + rl + 8) * C_ + col;
            float2 v0 = make_float2(fmaxf(acc[mt][nt][0] + bv.x, 0.f), fmaxf(acc[mt][nt][1] + bv.y, 0.f));
            float2 v1 = make_float2(fmaxf(acc[mt][nt][2] + bv.x, 0.f), fmaxf(acc[mt][nt][3] + bv.y, 0.f));
            const float2 q0 = *(const float2*)(in + r0);
            const float2 q1 = *(const float2*)(in + r1);
            v0.x += q0.x; v0.y += q0.y; v1.x += q1.x; v1.y += q1.y;
            *(float2*)(out + r0) = v0;
            *(float2*)(out + r1) = v1;
        }
    }
}

// =====================================================================
// Generic tf32 GEMM (512 threads) with optional LN-on-load, relu, residual
// =====================================================================
template<bool LNA, bool RELU, bool ADDRES>
__global__ void __launch_bounds__(512) k_gemm_tf32(
    const float* __restrict__ A, const float* __restrict__ W,
    const float* __restrict__ bias, const float* __restrict__ res,
    float* __restrict__ out,
    const float* __restrict__ g, const float* __restrict__ bb)
{
    extern __shared__ float sm[];
    float* As = sm;
    float* Ws = sm + 128 * 132;
    const int tid = threadIdx.x;
    const int m0 = blockIdx.x * 128;
    const int warp = tid >> 5, lane = tid & 31;

    if (LNA) {
        const float4 gg = *(const float4*)(g  + lane * 4);
        const float4 gb = *(const float4*)(bb + lane * 4);
        for (int r = warp; r < 128; r += 16) {
            float4 v = *(const float4*)(A + (size_t)(m0 + r) * C_ + lane * 4);
            ln_row(v, gg, gb);
            uint4 u;
            u.x = cvt_tf32(v.x); u.y = cvt_tf32(v.y); u.z = cvt_tf32(v.z); u.w = cvt_tf32(v.w);
            *(uint4*)&As[r * 132 + lane * 4] = u;
        }
    } else {
        #pragma unroll
        for (int i = 0; i < 8; i++) {
            const int f4 = tid + i * 512;
            const int row = f4 >> 5, c = (f4 & 31) * 4;
            float4 a = *(const float4*)(A + (size_t)(m0 + row) * C_ + c);
            uint4 u;
            u.x = cvt_tf32(a.x); u.y = cvt_tf32(a.y); u.z = cvt_tf32(a.z); u.w = cvt_tf32(a.w);
            *(uint4*)&As[row * 132 + c] = u;
        }
    }
    #pragma unroll
    for (int i = 0; i < 8; i++) {
        const int f4 = tid + i * 512;
        const int row = f4 >> 5, c = (f4 & 31) * 4;
        float4 wv = *(const float4*)(W + (size_t)row * C_ + c);
        uint4 uw;
        uw.x = cvt_tf32(wv.x); uw.y = cvt_tf32(wv.y); uw.z = cvt_tf32(wv.z); uw.w = cvt_tf32(wv.w);
        *(uint4*)&Ws[row * 132 + c] = uw;
    }
    __syncthreads();

    const int grp = lane >> 2, tig = lane & 3;
    const int mw = warp >> 2, nw = warp & 3;
    float acc[2][4][4];
    #pragma unroll
    for (int mt = 0; mt < 2; mt++)
        #pragma unroll
        for (int nt = 0; nt < 4; nt++)
            #pragma unroll
            for (int q = 0; q < 4; q++) acc[mt][nt][q] = 0.f;

    mma_128x128((const unsigned*)As, (const unsigned*)Ws, mw, nw, grp, tig, acc);

    #pragma unroll
    for (int nt = 0; nt < 4; nt++) {
        const int col = nw * 32 + nt * 8 + tig * 2;
        const float2 bv = *(const float2*)(bias + col);
        #pragma unroll
        for (int mt = 0; mt < 2; mt++) {
            const int row = m0 + mw * 32 + mt * 16 + grp;
            float2 v0 = make_float2(acc[mt][nt][0] + bv.x, acc[mt][nt][1] + bv.y);
            float2 v1 = make_float2(acc[mt][nt][2] + bv.x, acc[mt][nt][3] + bv.y);
            if (RELU) {
                v0.x = fmaxf(v0.x, 0.f); v0.y = fmaxf(v0.y, 0.f);
                v1.x = fmaxf(v1.x, 0.f); v1.y = fmaxf(v1.y, 0.f);
            }
            if (ADDRES) {
                const float2 r0 = *(const float2*)(res + (size_t)row * C_ + col);
                const float2 r1 = *(const float2*)(res + (size_t)(row + 8) * C_ + col);
                v0.x += r0.x; v0.y += r0.y; v1.x += r1.x; v1.y += r1.y;
            }
            *(float2*)(out + (size_t)row * C_ + col) = v0;
            *(float2*)(out + (size_t)(row + 8) * C_ + col) = v1;
        }
    }
}

// =====================================================================
// Fused QKV (512 threads): LN(A) once, three weights, three outputs
// =====================================================================
__global__ void __launch_bounds__(512) k_qkv3(
    const float* __restrict__ A,
    const float* __restrict__ wq, const float* __restrict__ bq, float* __restrict__ oq,
    const float* __restrict__ wk, const float* __restrict__ bk, float* __restrict__ ok,
    const float* __restrict__ wv, const float* __restrict__ bv, float* __restrict__ ov,
    const float* __restrict__ g, const float* __restrict__ bb)
{
    extern __shared__ float sm[];
    float* As = sm;
    float* Ws = sm + 128 * 132;
    const int tid = threadIdx.x;
    const int m0 = blockIdx.x * 128;
    const int warp = tid >> 5, lane = tid & 31;

    {
        const float4 gg = *(const float4*)(g  + lane * 4);
        const float4 gb = *(const float4*)(bb + lane * 4);
        for (int r = warp; r < 128; r += 16) {
            float4 v = *(const float4*)(A + (size_t)(m0 + r) * C_ + lane * 4);
            ln_row(v, gg, gb);
            uint4 u;
            u.x = cvt_tf32(v.x); u.y = cvt_tf32(v.y); u.z = cvt_tf32(v.z); u.w = cvt_tf32(v.w);
            *(uint4*)&As[r * 132 + lane * 4] = u;
        }
    }

    const float* Wj[3]  = {wq, wk, wv};
    const float* bj[3]  = {bq, bk, bv};
    float*       outj[3] = {oq, ok, ov};

    const int grp = lane >> 2, tig = lane & 3;
    const int mw = warp >> 2, nw = warp & 3;

    #pragma unroll 1
    for (int j = 0; j < 3; j++) {
        __syncthreads();
        #pragma unroll
        for (int i = 0; i < 8; i++) {
            const int f4 = tid + i * 512;
            const int row = f4 >> 5, c = (f4 & 31) * 4;
            float4 wv4 = *(const float4*)(Wj[j] + (size_t)row * C_ + c);
            uint4 uw;
            uw.x = cvt_tf32(wv4.x); uw.y = cvt_tf32(wv4.y); uw.z = cvt_tf32(wv4.z); uw.w = cvt_tf32(wv4.w);
            *(uint4*)&Ws[row * 132 + c] = uw;
        }
        __syncthreads();

        float acc[2][4][4];
        #pragma unroll
        for (int mt = 0; mt < 2; mt++)
            #pragma unroll
            for (int nt = 0; nt < 4; nt++)
                #pragma unroll
                for (int q = 0; q < 4; q++) acc[mt][nt][q] = 0.f;

        mma_128x128((const unsigned*)As, (const unsigned*)Ws, mw, nw, grp, tig, acc);

        #pragma unroll
        for (int nt = 0; nt < 4; nt++) {
            const int col = nw * 32 + nt * 8 + tig * 2;
            const float2 bvv = *(const float2*)(bj[j] + col);
            #pragma unroll
            for (int mt = 0; mt < 2; mt++) {
                const int row = m0 + mw * 32 + mt * 16 + grp;
                float2 v0 = make_float2(acc[mt][nt][0] + bvv.x, acc[mt][nt][1] + bvv.y);
                float2 v1 = make_float2(acc[mt][nt][2] + bvv.x, acc[mt][nt][3] + bvv.y);
                *(float2*)(outj[j] + (size_t)row * C_ + col) = v0;
                *(float2*)(outj[j] + (size_t)(row + 8) * C_ + col) = v1;
            }
        }
    }
}

// ---------------- flash attention (no-max softmax, pipelined K/V) ----------------
__global__ void __launch_bounds__(256) k_attn(
    const float* __restrict__ Q, const float* __restrict__ K,
    const float* __restrict__ V, const void* __restrict__ maskp,
    float* __restrict__ O)
{
    __shared__ __nv_bfloat16 Qs[128 * 24];
    __shared__ __nv_bfloat16 Ks[64 * 24];
    __shared__ __nv_bfloat16 Vs[64 * 24];
    __shared__ float msk[1024];
    const int tid = threadIdx.x;
    const int w = tid >> 5, l = tid & 31;
    const int grp = l >> 2, tig = l & 3;
    const int b = blockIdx.y >> 3, h = blockIdx.y & 7;
    const int q0 = blockIdx.x * 128;
    const int mint = g_mask_int;
    const int* mi = (const int*)maskp;
    const unsigned char* mu = (const unsigned char*)maskp;

    // full mask row for this batch, once
    #pragma unroll
    for (int i = tid; i < 1024; i += 256) {
        const int mv = mint ? mi[b * L_ + i] : (int)mu[b * L_ + i];
        msk[i] = mv ? -1e30f : 0.f;
    }
    // Q tile, pre-scaled by 0.25
    #pragma unroll
    for (int i = tid; i < 512; i += 256) {
        const int row = i >> 2, c4 = (i & 3) * 4;
        float4 f = *(const float4*)(Q + ((size_t)(b * L_ + q0 + row) * C_) + h * 16 + c4);
        __nv_bfloat162* dst = (__nv_bfloat162*)(Qs + row * 24 + c4);
        dst[0] = __floats2bfloat162_rn(f.x * 0.25f, f.y * 0.25f);
        dst[1] = __floats2bfloat162_rn(f.z * 0.25f, f.w * 0.25f);
    }
    __syncthreads();
    unsigned qa0, qa1, qa2, qa3;
    {
        const __nv_bfloat16* p = Qs + (w * 16 + (l & 15)) * 24 + ((l >> 4) * 8);
        unsigned ad = (unsigned)__cvta_generic_to_shared(p);
        LDMX4(qa0, qa1, qa2, qa3, ad);
    }

    float o0[4] = {0,0,0,0}, o1[4] = {0,0,0,0};
    float sum0 = 0.f, sum1 = 0.f;

    // pipeline: regs hold next tile
    const int krow = tid >> 2, kc4 = (tid & 3) * 4;
    float4 fk = *(const float4*)(K + ((size_t)(b * L_ + krow) * C_) + h * 16 + kc4);
    float4 fv = *(const float4*)(V + ((size_t)(b * L_ + krow) * C_) + h * 16 + kc4);

    for (int kt = 0; kt < 16; kt++) {
        __syncthreads();   // previous tile fully consumed
        {
            __nv_bfloat162* dk = (__nv_bfloat162*)(Ks + krow * 24 + kc4);
            dk[0] = __floats2bfloat162_rn(fk.x, fk.y);
            dk[1] = __floats2bfloat162_rn(fk.z, fk.w);
            __nv_bfloat162* dv = (__nv_bfloat162*)(Vs + krow * 24 + kc4);
            dv[0] = __floats2bfloat162_rn(fv.x, fv.y);
            dv[1] = __floats2bfloat162_rn(fv.z, fv.w);
        }
        __syncthreads();
        if (kt < 15) {
            const size_t base = ((size_t)(b * L_ + (kt + 1) * 64 + krow) * C_) + h * 16 + kc4;
            fk = *(const float4*)(K + base);
            fv = *(const float4*)(V + base);
        }
        const int k0 = kt * 64;

        float s[8][4];
        #pragma unroll
        for (int ntp = 0; ntp < 4; ntp++) {
            const int nb = ntp * 16;
            const __nv_bfloat16* p = Ks + (nb + ((l >> 4) & 1) * 8 + (l & 7)) * 24 + ((l >> 3) & 1) * 8;
            unsigned ad = (unsigned)__cvta_generic_to_shared(p);
            unsigned kb0, kb1, kb2, kb3;
            LDMX4(kb0, kb1, kb2, kb3, ad);
            MMA_BF16_Z(s[2*ntp],     qa0, qa1, qa2, qa3, kb0, kb1);
            MMA_BF16_Z(s[2*ntp + 1], qa0, qa1, qa2, qa3, kb2, kb3);
        }

        unsigned pa[4][4];
        #pragma unroll
        for (int nt = 0; nt < 8; nt++) {
            const float2 mk = *(const float2*)&msk[k0 + nt * 8 + tig * 2];
            const float p0 = __expf(s[nt][0] + mk.x), p1 = __expf(s[nt][1] + mk.y);
            const float p2 = __expf(s[nt][2] + mk.x), p3 = __expf(s[nt][3] + mk.y);
            sum0 += p0 + p1; sum1 += p2 + p3;
            pa[nt >> 1][(nt & 1) * 2 + 0] = pack_bf16(p0, p1);
            pa[nt >> 1][(nt & 1) * 2 + 1] = pack_bf16(p2, p3);
        }

        #pragma unroll
        for (int kk = 0; kk < 4; kk++) {
            const __nv_bfloat16* p = Vs + (kk * 16 + ((l >> 3) & 1) * 8 + (l & 7)) * 24 + ((l >> 4) & 1) * 8;
            unsigned ad = (unsigned)__cvta_generic_to_shared(p);
            unsigned vb0, vb1, vb2, vb3;
            LDMX4T(vb0, vb1, vb2, vb3, ad);
            MMA_BF16(o0, pa[kk][0], pa[kk][1], pa[kk][2], pa[kk][3], vb0, vb1);
            MMA_BF16(o1, pa[kk][0], pa[kk][1], pa[kk][2], pa[kk][3], vb2, vb3);
        }
    }

    sum0 += __shfl_xor_sync(0xffffffffu, sum0, 1);
    sum0 += __shfl_xor_sync(0xffffffffu, sum0, 2);
    sum1 += __shfl_xor_sync(0xffffffffu, sum1, 1);
    sum1 += __shfl_xor_sync(0xffffffffu, sum1, 2);
    const float i0 = 1.f / sum0, i1 = 1.f / sum1;
    const int row0 = q0 + w * 16 + grp, row1 = row0 + 8;
    const int colb = h * 16 + tig * 2;
    *(float2*)(O + (size_t)(b * L_ + row0) * C_ + colb)     = make_float2(o0[0]*i0, o0[1]*i0);
    *(float2*)(O + (size_t)(b * L_ + row1) * C_ + colb)     = make_float2(o0[2]*i1, o0[3]*i1);
    *(float2*)(O + (size_t)(b * L_ + row0) * C_ + colb + 8) = make_float2(o1[0]*i0, o1[1]*i0);
    *(float2*)(O + (size_t)(b * L_ + row1) * C_ + colb + 8) = make_float2(o1[2]*i1, o1[3]*i1);
}

// ---------------- launcher ----------------
extern "C" void kernel_launch(void* const* d_in, const int* in_sizes, int n_in,
                              void* d_out, int out_size)
{
    const float* x    = (const float*)d_in[0];
    const void*  mask = d_in[1];
    const float* dw_w = (const float*)d_in[2];
    const float* pw_w = (const float*)d_in[3];
    const float* pw_b = (const float*)d_in[4];
    const float* ng   = (const float*)d_in[5];
    const float* nb   = (const float*)d_in[6];
    const float* wq = (const float*)d_in[7];   const float* bq = (const float*)d_in[8];
    const float* wk = (const float*)d_in[9];   const float* bk = (const float*)d_in[10];
    const float* wv = (const float*)d_in[11];  const float* bv = (const float*)d_in[12];
    const float* wo = (const float*)d_in[13];  const float* bo = (const float*)d_in[14];
    const float* w1 = (const float*)d_in[15];  const float* b1 = (const float*)d_in[16];
    const float* w2 = (const float*)d_in[17];  const float* b2 = (const float*)d_in[18];
    float* out = (float*)d_out;

    float *cur, *ln, *t1, *q, *k, *v;
    { void* p; cudaGetSymbolAddress(&p, g_cur); cur = (float*)p; }
    { void* p; cudaGetSymbolAddress(&p, g_ln);  ln  = (float*)p; }
    { void* p; cudaGetSymbolAddress(&p, g_t1);  t1  = (float*)p; }
    { void* p; cudaGetSymbolAddress(&p, g_q);   q   = (float*)p; }
    { void* p; cudaGetSymbolAddress(&p, g_k);   k   = (float*)p; }
    { void* p; cudaGetSymbolAddress(&p, g_v);   v   = (float*)p; }

    const int SMC = (134 * 132 + 2 * 128 * 132 + 896) * 4;  // 209504 B
    const int SMG = 2 * 128 * 132 * 4;                       // 135168 B
    cudaFuncSetAttribute(k_convblock, cudaFuncAttributeMaxDynamicSharedMemorySize, SMC);
    cudaFuncSetAttribute(k_qkv3, cudaFuncAttributeMaxDynamicSharedMemorySize, SMG);
    cudaFuncSetAttribute(k_gemm_tf32<false,false,true >, cudaFuncAttributeMaxDynamicSharedMemorySize, SMG);
    cudaFuncSetAttribute(k_gemm_tf32<true ,true ,false>, cudaFuncAttributeMaxDynamicSharedMemorySize, SMG);

    const dim3 tgrid(32, 4, 16), tblk(32, 8);

    k_detect_mask<<<1, 256>>>((const unsigned char*)mask);
    k_in2work<<<tgrid, tblk>>>(x, cur);

    const float* cin[4]  = {cur, t1, cur, t1};
    float*       cout[4] = {t1, cur, t1, cur};
    for (int i = 0; i < NCONV_; i++) {
        k_convblock<<<128, 512, SMC>>>(cin[i], dw_w + i * C_ * 7, pw_w + i * C_ * C_,
                                       pw_b + i * C_, ng + i * C_, nb + i * C_, cout[i]);
    }

    k_qkv3<<<128, 512, SMG>>>(cur, wq, bq, q, wk, bk, k, wv, bv, v,
                              ng + NCONV_ * C_, nb + NCONV_ * C_);
    k_attn<<<dim3(8, 128), 256>>>(q, k, v, mask, ln);
    k_gemm_tf32<false,false,true ><<<128, 512, SMG>>>(ln, wo, bo, cur, cur, nullptr, nullptr);

    k_gemm_tf32<true ,true ,false><<<128, 512, SMG>>>(cur, w1, b1, nullptr, t1,
                                                      ng + (NCONV_ + 1) * C_, nb + (NCONV_ + 1) * C_);
    k_gemm_tf32<false,false,true ><<<128, 512, SMG>>>(t1, w2, b2, cur, cur, nullptr, nullptr);

    k_work2out<<<tgrid, tblk>>>(cur, out);
}